// round 2
// baseline (speedup 1.0000x reference)
#include <cuda_runtime.h>
#include <cuda_bf16.h>

// Problem constants
#define BSZ   16384
#define DIM   64
#define D2    32
#define NF    8      // flow steps
#define HID   8

// smem float offsets
#define OFF_W0 0        // 8*4*8*32  = 8192
#define OFF_B0 8192     // 8*4*8     = 256
#define OFF_W1 8448     // 8*4*8*8   = 2048
#define OFF_B1 10496    // 8*4*8     = 256
#define OFF_W2 10752    // 8*4*32*8  = 8192
#define OFF_B2 18944    // 8*4*32    = 1024
#define SMEM_FLOATS 19968
#define SMEM_BYTES (SMEM_FLOATS * 4)

__device__ __forceinline__ float dot32(const float* __restrict__ w, const float* a) {
    float s0 = 0.f, s1 = 0.f, s2 = 0.f, s3 = 0.f;
#pragma unroll
    for (int i = 0; i < 32; i += 4) {
        s0 = fmaf(w[i+0], a[i+0], s0);
        s1 = fmaf(w[i+1], a[i+1], s1);
        s2 = fmaf(w[i+2], a[i+2], s2);
        s3 = fmaf(w[i+3], a[i+3], s3);
    }
    return (s0 + s1) + (s2 + s3);
}

__device__ __forceinline__ float dot8(const float* __restrict__ w, const float* a) {
    float s0 = 0.f, s1 = 0.f;
#pragma unroll
    for (int i = 0; i < 8; i += 2) {
        s0 = fmaf(w[i+0], a[i+0], s0);
        s1 = fmaf(w[i+1], a[i+1], s1);
    }
    return s0 + s1;
}

// h1 = tanh(W0 a + b0), h2 = tanh(W1 h1 + b1)
__device__ __forceinline__ void hiddens(const float* __restrict__ W0, const float* __restrict__ b0,
                                        const float* __restrict__ W1, const float* __restrict__ b1,
                                        const float* a, float* h1, float* h2) {
#pragma unroll
    for (int j = 0; j < HID; j++) h1[j] = tanhf(b0[j] + dot32(W0 + j * 32, a));
#pragma unroll
    for (int j = 0; j < HID; j++) h2[j] = tanhf(b1[j] + dot8(W1 + j * 8, h1));
}

// q = diag(1-h2^2) W1 diag(1-h1^2) W0 d   (JVP through hidden layers)
__device__ __forceinline__ void jvp_hidden(const float* __restrict__ W0, const float* __restrict__ W1,
                                           const float* h1, const float* h2,
                                           const float* d, float* q) {
    float p[HID];
#pragma unroll
    for (int j = 0; j < HID; j++) p[j] = (1.f - h1[j] * h1[j]) * dot32(W0 + j * 32, d);
#pragma unroll
    for (int j = 0; j < HID; j++) q[j] = (1.f - h2[j] * h2[j]) * dot8(W1 + j * 8, p);
}

__global__ __launch_bounds__(128, 1)
void nf_solve_kernel(const float* __restrict__ gX, const float* __restrict__ gXs,
                     const float* __restrict__ gW0, const float* __restrict__ gB0,
                     const float* __restrict__ gW1, const float* __restrict__ gB1,
                     const float* __restrict__ gW2, const float* __restrict__ gB2,
                     float* __restrict__ gOut) {
    extern __shared__ float sm[];
    const int tid = threadIdx.x;

    // cooperative weight load into smem
    for (int i = tid; i < 8192; i += blockDim.x) sm[OFF_W0 + i] = gW0[i];
    for (int i = tid; i < 256;  i += blockDim.x) sm[OFF_B0 + i] = gB0[i];
    for (int i = tid; i < 2048; i += blockDim.x) sm[OFF_W1 + i] = gW1[i];
    for (int i = tid; i < 256;  i += blockDim.x) sm[OFF_B1 + i] = gB1[i];
    for (int i = tid; i < 8192; i += blockDim.x) sm[OFF_W2 + i] = gW2[i];
    for (int i = tid; i < 1024; i += blockDim.x) sm[OFF_B2 + i] = gB2[i];
    __syncthreads();

    const int b = blockIdx.x * blockDim.x + tid;
    if (b >= BSZ) return;

    const float* x  = gX  + (size_t)b * DIM;
    const float* xs = gXs + (size_t)b * DIM;

    float lo[D2], up[D2];
#pragma unroll
    for (int i = 0; i < D2; i++) { lo[i] = x[i]; up[i] = x[D2 + i]; }

    float h1a[HID], h2a[HID], h1b[HID], h2b[HID];

    // ---------- forward: z = phi(x) ----------
    for (int k = 0; k < NF; k++) {
        const float* W0k = sm + OFF_W0 + k * 1024;  // branch stride 256
        const float* B0k = sm + OFF_B0 + k * 32;    // branch stride 8
        const float* W1k = sm + OFF_W1 + k * 256;   // branch stride 64
        const float* B1k = sm + OFF_B1 + k * 32;    // branch stride 8
        const float* W2k = sm + OFF_W2 + k * 1024;  // branch stride 256, row stride 8
        const float* B2k = sm + OFF_B2 + k * 128;   // branch stride 32

        // up' = t1(lo) + up * exp(s1(lo))
        hiddens(W0k + 0 * 256, B0k + 0 * 8, W1k + 0 * 64, B1k + 0 * 8, lo, h1a, h2a);
        hiddens(W0k + 1 * 256, B0k + 1 * 8, W1k + 1 * 64, B1k + 1 * 8, lo, h1b, h2b);
#pragma unroll
        for (int i = 0; i < D2; i++) {
            float t = B2k[0 * 32 + i] + dot8(W2k + 0 * 256 + i * 8, h2a);
            float s = B2k[1 * 32 + i] + dot8(W2k + 1 * 256 + i * 8, h2b);
            up[i] = fmaf(up[i], expf(s), t);
        }
        // lo' = t2(up') + lo * exp(s2(up'))
        hiddens(W0k + 2 * 256, B0k + 2 * 8, W1k + 2 * 64, B1k + 2 * 8, up, h1a, h2a);
        hiddens(W0k + 3 * 256, B0k + 3 * 8, W1k + 3 * 64, B1k + 3 * 8, up, h1b, h2b);
#pragma unroll
        for (int i = 0; i < D2; i++) {
            float t = B2k[2 * 32 + i] + dot8(W2k + 2 * 256 + i * 8, h2a);
            float s = B2k[3 * 32 + i] + dot8(W2k + 3 * 256 + i * 8, h2b);
            lo[i] = fmaf(lo[i], expf(s), t);
        }
    }

    // ---------- rhs: g = -2 (x - x_star) ----------
    float ylo[D2], yup[D2];
#pragma unroll
    for (int i = 0; i < D2; i++) {
        ylo[i] = -2.f * (x[i]      - xs[i]);
        yup[i] = -2.f * (x[D2 + i] - xs[D2 + i]);
    }

    // ---------- backward: y <- J_k^{-1} y, reconstructing states exactly ----------
    // J_step = [[I, C],[0, I]] * [[diag(e^{s2}),0],[B, diag(e^{s1})]]
    //   C = J_t2 + diag(lo * e^{s2}) J_s2,  lo*e^{s2} = lo' - t2
    //   B = J_t1 + diag(up * e^{s1}) J_s1,  up*e^{s1} = up' - t1
    float qt[HID], qs[HID];
    for (int k = NF - 1; k >= 0; k--) {
        const float* W0k = sm + OFF_W0 + k * 1024;
        const float* B0k = sm + OFF_B0 + k * 32;
        const float* W1k = sm + OFF_W1 + k * 256;
        const float* B1k = sm + OFF_B1 + k * 32;
        const float* W2k = sm + OFF_W2 + k * 1024;
        const float* B2k = sm + OFF_B2 + k * 128;

        // Phase A: invert lo update. hiddens of t2 (br2), s2 (br3) at up'.
        hiddens(W0k + 2 * 256, B0k + 2 * 8, W1k + 2 * 64, B1k + 2 * 8, up, h1a, h2a);
        hiddens(W0k + 3 * 256, B0k + 3 * 8, W1k + 3 * 64, B1k + 3 * 8, up, h1b, h2b);
        // JVP hiddens with direction y_up
        jvp_hidden(W0k + 2 * 256, W1k + 2 * 64, h1a, h2a, yup, qt);
        jvp_hidden(W0k + 3 * 256, W1k + 3 * 64, h1b, h2b, yup, qs);
#pragma unroll
        for (int i = 0; i < D2; i++) {
            const float* w2t = W2k + 2 * 256 + i * 8;
            const float* w2s = W2k + 3 * 256 + i * 8;
            float t2 = B2k[2 * 32 + i] + dot8(w2t, h2a);
            float s2 = B2k[3 * 32 + i] + dot8(w2s, h2b);
            float d  = lo[i] - t2;          // = lo_prev * e^{s2}
            float e  = expf(-s2);
            lo[i]    = d * e;               // reconstructed pre-step lo
            float cv = dot8(w2t, qt) + d * dot8(w2s, qs);   // (C y_up)_i
            ylo[i]   = (ylo[i] - cv) * e;
        }

        // Phase B: invert up update. hiddens of t1 (br0), s1 (br1) at lo (pre-step).
        hiddens(W0k + 0 * 256, B0k + 0 * 8, W1k + 0 * 64, B1k + 0 * 8, lo, h1a, h2a);
        hiddens(W0k + 1 * 256, B0k + 1 * 8, W1k + 1 * 64, B1k + 1 * 8, lo, h1b, h2b);
        // JVP hiddens with direction (updated) y_lo
        jvp_hidden(W0k + 0 * 256, W1k + 0 * 64, h1a, h2a, ylo, qt);
        jvp_hidden(W0k + 1 * 256, W1k + 1 * 64, h1b, h2b, ylo, qs);
#pragma unroll
        for (int i = 0; i < D2; i++) {
            const float* w2t = W2k + 0 * 256 + i * 8;
            const float* w2s = W2k + 1 * 256 + i * 8;
            float t1 = B2k[0 * 32 + i] + dot8(w2t, h2a);
            float s1 = B2k[1 * 32 + i] + dot8(w2s, h2b);
            float d  = up[i] - t1;          // = up_prev * e^{s1}
            float e  = expf(-s1);
            up[i]    = d * e;               // reconstructed pre-step up
            float bv = dot8(w2t, qt) + d * dot8(w2s, qs);   // (B y_lo)_i
            yup[i]   = (yup[i] - bv) * e;
        }
    }

    float* out = gOut + (size_t)b * DIM;
#pragma unroll
    for (int i = 0; i < D2; i++) { out[i] = ylo[i]; out[D2 + i] = yup[i]; }
}

extern "C" void kernel_launch(void* const* d_in, const int* in_sizes, int n_in,
                              void* d_out, int out_size) {
    const float* x  = (const float*)d_in[0];
    const float* xs = (const float*)d_in[1];
    const float* W0 = (const float*)d_in[2];
    const float* b0 = (const float*)d_in[3];
    const float* W1 = (const float*)d_in[4];
    const float* b1 = (const float*)d_in[5];
    const float* W2 = (const float*)d_in[6];
    const float* b2 = (const float*)d_in[7];
    float* out = (float*)d_out;

    cudaFuncSetAttribute(nf_solve_kernel, cudaFuncAttributeMaxDynamicSharedMemorySize, SMEM_BYTES);
    nf_solve_kernel<<<(BSZ + 127) / 128, 128, SMEM_BYTES>>>(x, xs, W0, b0, W1, b1, W2, b2, out);
}

// round 4
// speedup vs baseline: 1.5174x; 1.5174x over previous
#include <cuda_runtime.h>
#include <cuda_bf16.h>

typedef unsigned long long ull;

#define BSZ   16384
#define NF    8
#define TPB   64

// smem float offsets
#define OFF_W0 0        // 8*4*8*32  = 8192
#define OFF_B0 8192     // 8*4*8     = 256
#define OFF_W1 8448     // 8*4*8*8   = 2048
#define OFF_B1 10496    // 8*4*8     = 256
#define OFF_W2 10752    // 8*4*32*8  = 8192
#define OFF_B2 18944    // 8*4*32    = 1024
#define OFF_Y  19968    // 64 threads * 66 floats scratch (ylo[32], yup[32], pad 2)
#define Y_STRIDE 66
#define SMEM_FLOATS (OFF_Y + TPB * Y_STRIDE)
#define SMEM_BYTES  (SMEM_FLOATS * 4)

// ---------------- packed f32x2 helpers ----------------
__device__ __forceinline__ ull ffma2u(ull a, ull b, ull c) {
    asm("fma.rn.f32x2 %0, %1, %2, %0;" : "+l"(c) : "l"(a), "l"(b));
    return c;
}
__device__ __forceinline__ ull f2u(float x, float y) {
    ull u; asm("mov.b64 %0, {%1, %2};" : "=l"(u) : "f"(x), "f"(y)); return u;
}
__device__ __forceinline__ void u2ff(ull u, float& x, float& y) {
    asm("mov.b64 {%0, %1}, %2;" : "=f"(x), "=f"(y) : "l"(u));
}
__device__ __forceinline__ ull ld2u(const float2* p) {
    float2 v = *p;
    ull u; asm("mov.b64 %0, {%1, %2};" : "=l"(u) : "f"(v.x), "f"(v.y)); return u;
}
__device__ __forceinline__ float redu(ull u) {
    float x, y; u2ff(u, x, y); return x + y;
}
__device__ __forceinline__ float tanhfast(float x) {
    float e = __expf(2.f * x);
    return 1.f - __fdividef(2.f, e + 1.f);
}

// ---------------- per-(step, branch-pair) weight pointers ----------------
struct FP {
    const float2 *w0t, *w0s, *w1t, *w1s, *w2t, *w2s;
    const float  *b0t, *b0s, *b1t, *b1s, *b2t, *b2s;
};
__device__ __forceinline__ FP mkfp(const float* sm, int k, int bT) {
    FP p;
    const int iT = k * 4 + bT, iS = iT + 1;
    p.w0t = (const float2*)(sm + OFF_W0 + iT * 256);
    p.w0s = (const float2*)(sm + OFF_W0 + iS * 256);
    p.w1t = (const float2*)(sm + OFF_W1 + iT * 64);
    p.w1s = (const float2*)(sm + OFF_W1 + iS * 64);
    p.w2t = (const float2*)(sm + OFF_W2 + iT * 256);
    p.w2s = (const float2*)(sm + OFF_W2 + iS * 256);
    p.b0t = sm + OFF_B0 + iT * 8;  p.b0s = sm + OFF_B0 + iS * 8;
    p.b1t = sm + OFF_B1 + iT * 8;  p.b1s = sm + OFF_B1 + iS * 8;
    p.b2t = sm + OFF_B2 + iT * 32; p.b2s = sm + OFF_B2 + iS * 32;
    return p;
}

// ---------------- forward: both branches' h2 (packed) ----------------
__device__ __forceinline__ void fcnn_h2(const FP& P, const ull (&a)[16],
                                        ull (&h2t)[4], ull (&h2s)[4]) {
    ull at[8], as_[8];
#pragma unroll
    for (int j = 0; j < 8; j++) { at[j] = 0ull; as_[j] = 0ull; }
#pragma unroll
    for (int m = 0; m < 16; m++) {
        ull aa = a[m];
#pragma unroll
        for (int j = 0; j < 8; j++) {
            at[j]  = ffma2u(ld2u(P.w0t + j * 16 + m), aa, at[j]);
            as_[j] = ffma2u(ld2u(P.w0s + j * 16 + m), aa, as_[j]);
        }
    }
    float h1t[8], h1s[8];
#pragma unroll
    for (int j = 0; j < 8; j++) {
        h1t[j] = tanhfast(P.b0t[j] + redu(at[j]));
        h1s[j] = tanhfast(P.b0s[j] + redu(as_[j]));
    }
    ull h1t2[4], h1s2[4];
#pragma unroll
    for (int c = 0; c < 4; c++) {
        h1t2[c] = f2u(h1t[2 * c], h1t[2 * c + 1]);
        h1s2[c] = f2u(h1s[2 * c], h1s[2 * c + 1]);
    }
    float pvT = 0.f, pvS = 0.f;
#pragma unroll
    for (int j = 0; j < 8; j++) {
        ull acT = 0ull, acS = 0ull;
#pragma unroll
        for (int c = 0; c < 4; c++) {
            acT = ffma2u(ld2u(P.w1t + j * 4 + c), h1t2[c], acT);
            acS = ffma2u(ld2u(P.w1s + j * 4 + c), h1s2[c], acS);
        }
        float vT = tanhfast(P.b1t[j] + redu(acT));
        float vS = tanhfast(P.b1s[j] + redu(acS));
        if (j & 1) { h2t[j >> 1] = f2u(pvT, vT); h2s[j >> 1] = f2u(pvS, vS); }
        else       { pvT = vT; pvS = vS; }
    }
}

// v[i] = t(a)[i] + v[i] * exp(s(a)[i])
__device__ __forceinline__ void fwd_phase(const FP& P, const ull (&a)[16], ull (&v)[16]) {
    ull h2t[4], h2s[4];
    fcnn_h2(P, a, h2t, h2s);
#pragma unroll
    for (int m = 0; m < 16; m++) {
        float tt[2], ss[2];
#pragma unroll
        for (int half = 0; half < 2; half++) {
            const int i = 2 * m + half;
            ull aT = 0ull, aS = 0ull;
#pragma unroll
            for (int c = 0; c < 4; c++) {
                aT = ffma2u(ld2u(P.w2t + i * 4 + c), h2t[c], aT);
                aS = ffma2u(ld2u(P.w2s + i * 4 + c), h2s[c], aS);
            }
            tt[half] = P.b2t[i] + redu(aT);
            ss[half] = P.b2s[i] + redu(aS);
        }
        float vx, vy; u2ff(v[m], vx, vy);
        vx = fmaf(vx, __expf(ss[0]), tt[0]);
        vy = fmaf(vy, __expf(ss[1]), tt[1]);
        v[m] = f2u(vx, vy);
    }
}

// Invert one coupling phase: given a (fcnn input, stays), u (the transformed half),
// d = y of the 'a' half (smem), yu = y of the 'u' half (smem, rmw).
//   u_new = (u - t(a)) * exp(-s(a))        (state reconstruction)
//   yu    = (yu - C yd) * exp(-s(a)),  C = J_t + diag(u - t) J_s
__device__ __forceinline__ void bwd_phase(const FP& P, const ull (&a)[16], ull (&u)[16],
                                          const float* yd, float* yu) {
    // fused layer-0: hiddens (input a) + JVP (direction d) for both branches,
    // each W0 element read once
    ull aHt[8], aDt[8], aHs[8], aDs[8];
#pragma unroll
    for (int j = 0; j < 8; j++) { aHt[j] = 0ull; aDt[j] = 0ull; aHs[j] = 0ull; aDs[j] = 0ull; }
    const float2* d2 = (const float2*)yd;
#pragma unroll
    for (int m = 0; m < 16; m++) {
        ull aa = a[m];
        ull dd = ld2u(d2 + m);
#pragma unroll
        for (int j = 0; j < 8; j++) {
            ull wt = ld2u(P.w0t + j * 16 + m);
            ull ws = ld2u(P.w0s + j * 16 + m);
            aHt[j] = ffma2u(wt, aa, aHt[j]);
            aDt[j] = ffma2u(wt, dd, aDt[j]);
            aHs[j] = ffma2u(ws, aa, aHs[j]);
            aDs[j] = ffma2u(ws, dd, aDs[j]);
        }
    }
    float h1t[8], h1s[8], pt[8], ps[8];
#pragma unroll
    for (int j = 0; j < 8; j++) {
        float vt = tanhfast(P.b0t[j] + redu(aHt[j]));
        h1t[j] = vt; pt[j] = (1.f - vt * vt) * redu(aDt[j]);
        float vs = tanhfast(P.b0s[j] + redu(aHs[j]));
        h1s[j] = vs; ps[j] = (1.f - vs * vs) * redu(aDs[j]);
    }
    ull h1t2[4], h1s2[4], pt2[4], ps2[4];
#pragma unroll
    for (int c = 0; c < 4; c++) {
        h1t2[c] = f2u(h1t[2 * c], h1t[2 * c + 1]);
        h1s2[c] = f2u(h1s[2 * c], h1s[2 * c + 1]);
        pt2[c]  = f2u(pt[2 * c],  pt[2 * c + 1]);
        ps2[c]  = f2u(ps[2 * c],  ps[2 * c + 1]);
    }
    // fused layer-1: h2 + q for both branches, each W1 element read once
    ull h2t2[4], h2s2[4], qt2[4], qs2[4];
    float pvT = 0.f, pvS = 0.f, pqT = 0.f, pqS = 0.f;
#pragma unroll
    for (int j = 0; j < 8; j++) {
        ull aH = 0ull, aQ = 0ull, bH = 0ull, bQ = 0ull;
#pragma unroll
        for (int c = 0; c < 4; c++) {
            ull w1t_ = ld2u(P.w1t + j * 4 + c);
            ull w1s_ = ld2u(P.w1s + j * 4 + c);
            aH = ffma2u(w1t_, h1t2[c], aH);
            aQ = ffma2u(w1t_, pt2[c],  aQ);
            bH = ffma2u(w1s_, h1s2[c], bH);
            bQ = ffma2u(w1s_, ps2[c],  bQ);
        }
        float h2tv = tanhfast(P.b1t[j] + redu(aH));
        float qtv  = (1.f - h2tv * h2tv) * redu(aQ);
        float h2sv = tanhfast(P.b1s[j] + redu(bH));
        float qsv  = (1.f - h2sv * h2sv) * redu(bQ);
        if (j & 1) {
            h2t2[j >> 1] = f2u(pvT, h2tv); qt2[j >> 1] = f2u(pqT, qtv);
            h2s2[j >> 1] = f2u(pvS, h2sv); qs2[j >> 1] = f2u(pqS, qsv);
        } else { pvT = h2tv; pqT = qtv; pvS = h2sv; pqS = qsv; }
    }
    // outputs: per index i, W2 rows read once, used for (t,cv_t) and (s,cv_s)
#pragma unroll
    for (int m = 0; m < 16; m++) {
        float ux, uy; u2ff(u[m], ux, uy);
        float nx = 0.f, ny = 0.f;
#pragma unroll
        for (int half = 0; half < 2; half++) {
            const int i = 2 * m + half;
            ull aT = 0ull, aC = 0ull, aS = 0ull, aD = 0ull;
#pragma unroll
            for (int c = 0; c < 4; c++) {
                ull w2t_ = ld2u(P.w2t + i * 4 + c);
                ull w2s_ = ld2u(P.w2s + i * 4 + c);
                aT = ffma2u(w2t_, h2t2[c], aT);
                aC = ffma2u(w2t_, qt2[c],  aC);
                aS = ffma2u(w2s_, h2s2[c], aS);
                aD = ffma2u(w2s_, qs2[c],  aD);
            }
            float t = P.b2t[i] + redu(aT);
            float s = P.b2s[i] + redu(aS);
            float uu = half ? uy : ux;
            float d  = uu - t;                      // = u_prev * e^{s}
            float e  = __expf(-s);
            float cv = redu(aC) + d * redu(aD);     // (C * yd)_i
            yu[i]    = (yu[i] - cv) * e;
            if (half) ny = d * e; else nx = d * e;
        }
        u[m] = f2u(nx, ny);
    }
}

__global__ __launch_bounds__(TPB, 1)
void nf2_kernel(const float* __restrict__ gX, const float* __restrict__ gXs,
                const float* __restrict__ gW0, const float* __restrict__ gB0,
                const float* __restrict__ gW1, const float* __restrict__ gB1,
                const float* __restrict__ gW2, const float* __restrict__ gB2,
                float* __restrict__ gOut) {
    extern __shared__ float sm[];
    const int tid = threadIdx.x;
    for (int i = tid; i < 8192; i += TPB) sm[OFF_W0 + i] = gW0[i];
    for (int i = tid; i < 256;  i += TPB) sm[OFF_B0 + i] = gB0[i];
    for (int i = tid; i < 2048; i += TPB) sm[OFF_W1 + i] = gW1[i];
    for (int i = tid; i < 256;  i += TPB) sm[OFF_B1 + i] = gB1[i];
    for (int i = tid; i < 8192; i += TPB) sm[OFF_W2 + i] = gW2[i];
    for (int i = tid; i < 1024; i += TPB) sm[OFF_B2 + i] = gB2[i];
    __syncthreads();

    const int b = blockIdx.x * TPB + tid;
    const float2* xr = (const float2*)(gX + (size_t)b * 64);

    ull lo[16], up[16];
#pragma unroll
    for (int m = 0; m < 16; m++) { lo[m] = ld2u(xr + m); up[m] = ld2u(xr + 16 + m); }

    // ---------- forward: z = phi(x) ----------
    for (int k = 0; k < NF; k++) {
        FP P01 = mkfp(sm, k, 0);
        fwd_phase(P01, lo, up);          // up' = t1(lo) + up*exp(s1(lo))
        FP P23 = mkfp(sm, k, 2);
        fwd_phase(P23, up, lo);          // lo' = t2(up') + lo*exp(s2(up'))
    }

    // ---------- rhs into smem scratch ----------
    float* ys = sm + OFF_Y + tid * Y_STRIDE;       // [0..31]=ylo, [32..63]=yup
    const float2* xsr = (const float2*)(gXs + (size_t)b * 64);
#pragma unroll
    for (int m = 0; m < 16; m++) {
        float ax, ay, bx, by;
        u2ff(ld2u(xr + m), ax, ay); u2ff(ld2u(xsr + m), bx, by);
        ((float2*)ys)[m] = make_float2(-2.f * (ax - bx), -2.f * (ay - by));
        u2ff(ld2u(xr + 16 + m), ax, ay); u2ff(ld2u(xsr + 16 + m), bx, by);
        ((float2*)(ys + 32))[m] = make_float2(-2.f * (ax - bx), -2.f * (ay - by));
    }

    // ---------- backward: y <- J_k^{-1} y with exact state reconstruction ----------
    for (int k = NF - 1; k >= 0; k--) {
        FP P23 = mkfp(sm, k, 2);
        bwd_phase(P23, up, lo, ys + 32, ys);   // invert lo-update; reconstruct lo
        FP P01 = mkfp(sm, k, 0);
        bwd_phase(P01, lo, up, ys, ys + 32);   // invert up-update; reconstruct up
    }

    float2* orow = (float2*)(gOut + (size_t)b * 64);
#pragma unroll
    for (int m = 0; m < 16; m++) {
        orow[m]      = ((float2*)ys)[m];
        orow[16 + m] = ((float2*)(ys + 32))[m];
    }
}

extern "C" void kernel_launch(void* const* d_in, const int* in_sizes, int n_in,
                              void* d_out, int out_size) {
    const float* x  = (const float*)d_in[0];
    const float* xs = (const float*)d_in[1];
    const float* W0 = (const float*)d_in[2];
    const float* b0 = (const float*)d_in[3];
    const float* W1 = (const float*)d_in[4];
    const float* b1 = (const float*)d_in[5];
    const float* W2 = (const float*)d_in[6];
    const float* b2 = (const float*)d_in[7];
    float* out = (float*)d_out;

    cudaFuncSetAttribute(nf2_kernel, cudaFuncAttributeMaxDynamicSharedMemorySize, SMEM_BYTES);
    nf2_kernel<<<BSZ / TPB, TPB, SMEM_BYTES>>>(x, xs, W0, b0, W1, b1, W2, b2, out);
}

// round 5
// speedup vs baseline: 1.5332x; 1.0104x over previous
#include <cuda_runtime.h>
#include <cuda_bf16.h>

typedef unsigned long long ull;

#define BSZ   16384
#define NF    8
#define TPB   128          // 64 samples per block, 2 threads per sample
#define SPB   (TPB / 2)

// skewed smem weight layout (float offsets); strides chosen so the T-lane and
// S-lane broadcast addresses land on disjoint banks (stride % 128B == 16/32B)
#define W0_STR 264         // 256 + 8 pad   (1056B % 128 = 32)
#define W1_STR 72          // 64 + 8 pad    (288B  % 128 = 32)
#define W2_STR 264
#define B2_STR 36          // 32 + 4 pad    (144B  % 128 = 16)

#define OFF_W0 0                       // 32*264 = 8448
#define OFF_W1 8448                    // 32*72  = 2304
#define OFF_W2 10752                   // 32*264 = 8448
#define OFF_B0 19200                   // 32*8   = 256
#define OFF_B1 19456                   // 256
#define OFF_B2 19712                   // 32*36  = 1152
#define OFF_Y  20864                   // SPB*66 = 4224
#define Y_STRIDE 66
#define SMEM_FLOATS (OFF_Y + SPB * Y_STRIDE)
#define SMEM_BYTES  (SMEM_FLOATS * 4)

// ---------------- packed f32x2 helpers ----------------
__device__ __forceinline__ ull ffma2u(ull a, ull b, ull c) {
    asm("fma.rn.f32x2 %0, %1, %2, %0;" : "+l"(c) : "l"(a), "l"(b));
    return c;
}
__device__ __forceinline__ ull f2u(float x, float y) {
    ull u; asm("mov.b64 %0, {%1, %2};" : "=l"(u) : "f"(x), "f"(y)); return u;
}
__device__ __forceinline__ void u2ff(ull u, float& x, float& y) {
    asm("mov.b64 {%0, %1}, %2;" : "=f"(x), "=f"(y) : "l"(u));
}
__device__ __forceinline__ ull ld2u(const float2* p) {
    float2 v = *p;
    return f2u(v.x, v.y);
}
// one LDS.128 -> two packed f32x2 operands
__device__ __forceinline__ void ld4u(const float4* p, ull& u0, ull& u1) {
    float4 v = *p;
    u0 = f2u(v.x, v.y);
    u1 = f2u(v.z, v.w);
}
__device__ __forceinline__ float redu(ull u) {
    float x, y; u2ff(u, x, y); return x + y;
}
__device__ __forceinline__ float tanhfast(float x) {
    float e = __expf(2.f * x);
    return 1.f - __fdividef(2.f, e + 1.f);
}

// dot of 4 packed pairs (one 8-wide row) against h[4], via 2 LDS.128
__device__ __forceinline__ ull dot8p(const float4* row, const ull (&h)[4]) {
    ull c0, c1, c2, c3;
    ld4u(row, c0, c1);
    ld4u(row + 1, c2, c3);
    ull a = 0ull;
    a = ffma2u(c0, h[0], a);
    a = ffma2u(c1, h[1], a);
    a = ffma2u(c2, h[2], a);
    a = ffma2u(c3, h[3], a);
    return a;
}

// ---------------- forward phase (one branch per thread, role = 0:t / 1:s) ----
// v[i] = t(a)[i] + v[i] * exp(s(a)[i]) ; t from role-0 lane, s from role-1 lane
__device__ __forceinline__ void fwd_phase(const float* __restrict__ sm, int ib,
                                          const ull (&a)[16], ull (&v)[16], int role) {
    const float4* w0 = (const float4*)(sm + OFF_W0 + ib * W0_STR);
    const float4* w1 = (const float4*)(sm + OFF_W1 + ib * W1_STR);
    const float4* w2 = (const float4*)(sm + OFF_W2 + ib * W2_STR);
    const float*  b0 = sm + OFF_B0 + ib * 8;
    const float*  b1 = sm + OFF_B1 + ib * 8;
    const float*  b2 = sm + OFF_B2 + ib * B2_STR;

    ull acc[8];
#pragma unroll
    for (int j = 0; j < 8; j++) acc[j] = 0ull;
#pragma unroll
    for (int q = 0; q < 8; q++) {          // q covers packed m = 2q, 2q+1
        ull a0 = a[2 * q], a1 = a[2 * q + 1];
#pragma unroll
        for (int j = 0; j < 8; j++) {
            ull wA, wB;
            ld4u(w0 + j * 8 + q, wA, wB);
            acc[j] = ffma2u(wA, a0, acc[j]);
            acc[j] = ffma2u(wB, a1, acc[j]);
        }
    }
    float h1[8];
#pragma unroll
    for (int j = 0; j < 8; j++) h1[j] = tanhfast(b0[j] + redu(acc[j]));
    ull h1p[4];
#pragma unroll
    for (int c = 0; c < 4; c++) h1p[c] = f2u(h1[2 * c], h1[2 * c + 1]);

    float h2[8];
#pragma unroll
    for (int j = 0; j < 8; j++) h2[j] = tanhfast(b1[j] + redu(dot8p(w1 + j * 2, h1p)));
    ull h2p[4];
#pragma unroll
    for (int c = 0; c < 4; c++) h2p[c] = f2u(h2[2 * c], h2[2 * c + 1]);

#pragma unroll
    for (int m = 0; m < 16; m++) {
        float r0 = b2[2 * m]     + redu(dot8p(w2 + (2 * m) * 2, h2p));
        float r1 = b2[2 * m + 1] + redu(dot8p(w2 + (2 * m + 1) * 2, h2p));
        // role 1 turns its s-value into exp(s) before the exchange
        float s0 = role ? __expf(r0) : r0;
        float s1 = role ? __expf(r1) : r1;
        float o0 = __shfl_xor_sync(0xFFFFFFFFu, s0, 1);
        float o1 = __shfl_xor_sync(0xFFFFFFFFu, s1, 1);
        float t0 = role ? o0 : s0, e0 = role ? s0 : o0;
        float t1 = role ? o1 : s1, e1 = role ? s1 : o1;
        float vx, vy; u2ff(v[m], vx, vy);
        v[m] = f2u(fmaf(vx, e0, t0), fmaf(vy, e1, t1));
    }
}

// ---------------- backward phase ------------------------------------------
//   u_new = (u - t(a)) * exp(-s(a))
//   yu    = (yu - (J_t + diag(u - t) J_s) yd) * exp(-s(a))
__device__ __forceinline__ void bwd_phase(const float* __restrict__ sm, int ib,
                                          const ull (&a)[16], ull (&u)[16],
                                          const float* __restrict__ yd, float* yu, int role) {
    const float4* w0 = (const float4*)(sm + OFF_W0 + ib * W0_STR);
    const float4* w1 = (const float4*)(sm + OFF_W1 + ib * W1_STR);
    const float4* w2 = (const float4*)(sm + OFF_W2 + ib * W2_STR);
    const float*  b0 = sm + OFF_B0 + ib * 8;
    const float*  b1 = sm + OFF_B1 + ib * 8;
    const float*  b2 = sm + OFF_B2 + ib * B2_STR;

    // fused layer 0: hidden pre-acts (input a) + JVP pre-acts (direction yd)
    ull accH[8], accD[8];
#pragma unroll
    for (int j = 0; j < 8; j++) { accH[j] = 0ull; accD[j] = 0ull; }
    const float2* d2 = (const float2*)yd;
#pragma unroll
    for (int q = 0; q < 8; q++) {
        ull a0 = a[2 * q], a1 = a[2 * q + 1];
        ull d0 = ld2u(d2 + 2 * q), d1 = ld2u(d2 + 2 * q + 1);
#pragma unroll
        for (int j = 0; j < 8; j++) {
            ull wA, wB;
            ld4u(w0 + j * 8 + q, wA, wB);
            accH[j] = ffma2u(wA, a0, accH[j]);
            accD[j] = ffma2u(wA, d0, accD[j]);
            accH[j] = ffma2u(wB, a1, accH[j]);
            accD[j] = ffma2u(wB, d1, accD[j]);
        }
    }
    float h1[8], p[8];
#pragma unroll
    for (int j = 0; j < 8; j++) {
        float vt = tanhfast(b0[j] + redu(accH[j]));
        h1[j] = vt;
        p[j]  = (1.f - vt * vt) * redu(accD[j]);
    }
    ull h1p[4], pp[4];
#pragma unroll
    for (int c = 0; c < 4; c++) {
        h1p[c] = f2u(h1[2 * c], h1[2 * c + 1]);
        pp[c]  = f2u(p[2 * c],  p[2 * c + 1]);
    }

    // fused layer 1
    float h2[8], qv[8];
#pragma unroll
    for (int j = 0; j < 8; j++) {
        ull c0, c1, c2, c3;
        ld4u(w1 + j * 2,     c0, c1);
        ld4u(w1 + j * 2 + 1, c2, c3);
        ull aH = 0ull, aQ = 0ull;
        aH = ffma2u(c0, h1p[0], aH); aQ = ffma2u(c0, pp[0], aQ);
        aH = ffma2u(c1, h1p[1], aH); aQ = ffma2u(c1, pp[1], aQ);
        aH = ffma2u(c2, h1p[2], aH); aQ = ffma2u(c2, pp[2], aQ);
        aH = ffma2u(c3, h1p[3], aH); aQ = ffma2u(c3, pp[3], aQ);
        float vt = tanhfast(b1[j] + redu(aH));
        h2[j] = vt;
        qv[j] = (1.f - vt * vt) * redu(aQ);
    }
    ull h2p[4], qp[4];
#pragma unroll
    for (int c = 0; c < 4; c++) {
        h2p[c] = f2u(h2[2 * c], h2[2 * c + 1]);
        qp[c]  = f2u(qv[2 * c], qv[2 * c + 1]);
    }

    // layer 2 + exchange + inverse update
#pragma unroll
    for (int m = 0; m < 16; m++) {
        float ux, uy; u2ff(u[m], ux, uy);
        float un0 = 0.f, un1 = 0.f;
#pragma unroll
        for (int half = 0; half < 2; half++) {
            const int i = 2 * m + half;
            ull c0, c1, c2, c3;
            ld4u(w2 + i * 2,     c0, c1);
            ld4u(w2 + i * 2 + 1, c2, c3);
            ull aM = 0ull, aX = 0ull;
            aM = ffma2u(c0, h2p[0], aM); aX = ffma2u(c0, qp[0], aX);
            aM = ffma2u(c1, h2p[1], aM); aX = ffma2u(c1, qp[1], aX);
            aM = ffma2u(c2, h2p[2], aM); aX = ffma2u(c2, qp[2], aX);
            aM = ffma2u(c3, h2p[3], aM); aX = ffma2u(c3, qp[3], aX);
            float r = b2[i] + redu(aM);   // T: t_i   S: s_i
            float x = redu(aX);           // T: cT_i  S: dS_i
            float sendA = role ? __expf(-r) : r;     // T sends t, S sends e^-s
            float oA = __shfl_xor_sync(0xFFFFFFFFu, sendA, 1);
            float oB = __shfl_xor_sync(0xFFFFFFFFu, x, 1);
            float tt = role ? oA : sendA;
            float ee = role ? sendA : oA;
            float cT = role ? oB : x;
            float dS = role ? x : oB;
            float uu = half ? uy : ux;
            float d  = uu - tt;                      // = u_prev * e^{s}
            float unew = d * ee;
            if (half) un1 = unew; else un0 = unew;
            float cv = cT + d * dS;                  // (C * yd)_i
            if (!role) yu[i] = (yu[i] - cv) * ee;
        }
        u[m] = f2u(un0, un1);
    }
}

__global__ __launch_bounds__(TPB, 1)
void nf3_kernel(const float* __restrict__ gX, const float* __restrict__ gXs,
                const float* __restrict__ gW0, const float* __restrict__ gB0,
                const float* __restrict__ gW1, const float* __restrict__ gB1,
                const float* __restrict__ gW2, const float* __restrict__ gB2,
                float* __restrict__ gOut) {
    extern __shared__ float sm[];
    const int tid = threadIdx.x;

    // cooperative weight load with bank-skew layout
    for (int i = tid; i < 8192; i += TPB) sm[OFF_W0 + (i >> 8) * W0_STR + (i & 255)] = gW0[i];
    for (int i = tid; i < 2048; i += TPB) sm[OFF_W1 + (i >> 6) * W1_STR + (i & 63)]  = gW1[i];
    for (int i = tid; i < 8192; i += TPB) sm[OFF_W2 + (i >> 8) * W2_STR + (i & 255)] = gW2[i];
    for (int i = tid; i < 256;  i += TPB) sm[OFF_B0 + i] = gB0[i];
    for (int i = tid; i < 256;  i += TPB) sm[OFF_B1 + i] = gB1[i];
    for (int i = tid; i < 1024; i += TPB) sm[OFF_B2 + (i >> 5) * B2_STR + (i & 31)]  = gB2[i];
    __syncthreads();

    const int s_in_b = tid >> 1;
    const int role   = tid & 1;           // 0 = t-branches, 1 = s-branches
    const int samp   = blockIdx.x * SPB + s_in_b;

    const float2* xr = (const float2*)(gX + (size_t)samp * 64);
    ull lo[16], up[16];
#pragma unroll
    for (int m = 0; m < 16; m++) { lo[m] = ld2u(xr + m); up[m] = ld2u(xr + 16 + m); }

    // ---------- forward: z = phi(x) ----------
    for (int k = 0; k < NF; k++) {
        fwd_phase(sm, k * 4 + 0 + role, lo, up, role);   // up' = t1(lo) + up*exp(s1(lo))
        fwd_phase(sm, k * 4 + 2 + role, up, lo, role);   // lo' = t2(up') + lo*exp(s2(up'))
    }

    // ---------- rhs: g = -2 (x - x_star), role-split halves ----------
    float* ys = sm + OFF_Y + s_in_b * Y_STRIDE;          // [0..31]=ylo, [32..63]=yup
    {
        const float* xp  = gX  + (size_t)samp * 64 + role * 32;
        const float* xsp = gXs + (size_t)samp * 64 + role * 32;
        float* yh = ys + role * 32;
#pragma unroll
        for (int i = 0; i < 32; i++) yh[i] = -2.f * (xp[i] - xsp[i]);
    }
    __syncwarp();

    // ---------- backward: y <- J_k^{-1} y with exact state reconstruction ----------
    for (int k = NF - 1; k >= 0; k--) {
        bwd_phase(sm, k * 4 + 2 + role, up, lo, ys + 32, ys, role);   // invert lo-update
        __syncwarp();
        bwd_phase(sm, k * 4 + 0 + role, lo, up, ys, ys + 32, role);   // invert up-update
        __syncwarp();
    }

    // ---------- output: each role writes its half ----------
    float* op = gOut + (size_t)samp * 64 + role * 32;
    const float* yh = ys + role * 32;
#pragma unroll
    for (int i = 0; i < 32; i++) op[i] = yh[i];
}

extern "C" void kernel_launch(void* const* d_in, const int* in_sizes, int n_in,
                              void* d_out, int out_size) {
    const float* x  = (const float*)d_in[0];
    const float* xs = (const float*)d_in[1];
    const float* W0 = (const float*)d_in[2];
    const float* b0 = (const float*)d_in[3];
    const float* W1 = (const float*)d_in[4];
    const float* b1 = (const float*)d_in[5];
    const float* W2 = (const float*)d_in[6];
    const float* b2 = (const float*)d_in[7];
    float* out = (float*)d_out;

    cudaFuncSetAttribute(nf3_kernel, cudaFuncAttributeMaxDynamicSharedMemorySize, SMEM_BYTES);
    nf3_kernel<<<(BSZ * 2) / TPB, TPB, SMEM_BYTES>>>(x, xs, W0, b0, W1, b1, W2, b2, out);
}

// round 8
// speedup vs baseline: 1.5943x; 1.0398x over previous
#include <cuda_runtime.h>
#include <cuda_bf16.h>

typedef unsigned long long ull;

#define BSZ   16384
#define NF    8
#define TPB   512          // 128 samples/block, 4 lanes/sample
#define SPB   (TPB / 4)

// skewed smem weight layout (float offsets)
#define W0_RSTR 36         // row stride (144B): 4-row delta %128B = 64
#define W0_STR  296        // branch stride (1184B %128 = 32)
#define W1_RSTR 12         // 48B
#define W1_STR  104        // 416B %128 = 32
#define W2_STR  272        // dense 8-float rows; 1088B %128 = 64
#define B2_STR  36

#define OFF_W0 0                       // 32*296 = 9472
#define OFF_W1 9472                    // 32*104 = 3328
#define OFF_W2 12800                   // 32*272 = 8704
#define OFF_B0 21504                   // 256
#define OFF_B1 21760                   // 256
#define OFF_B2 22016                   // 32*36 = 1152
#define OFF_Y  23168                   // SPB*66 = 8448
#define Y_STRIDE 66
#define SMEM_FLOATS (OFF_Y + SPB * Y_STRIDE)
#define SMEM_BYTES  (SMEM_FLOATS * 4)

// ---------------- packed f32x2 helpers ----------------
__device__ __forceinline__ ull ffma2u(ull a, ull b, ull c) {
    asm("fma.rn.f32x2 %0, %1, %2, %0;" : "+l"(c) : "l"(a), "l"(b));
    return c;
}
__device__ __forceinline__ ull f2u(float x, float y) {
    ull u; asm("mov.b64 %0, {%1, %2};" : "=l"(u) : "f"(x), "f"(y)); return u;
}
__device__ __forceinline__ void u2ff(ull u, float& x, float& y) {
    asm("mov.b64 {%0, %1}, %2;" : "=f"(x), "=f"(y) : "l"(u));
}
__device__ __forceinline__ ull ld2u(const float2* p) {
    float2 v = *p; return f2u(v.x, v.y);
}
__device__ __forceinline__ void ld4u(const float4* p, ull& u0, ull& u1) {
    float4 v = *p; u0 = f2u(v.x, v.y); u1 = f2u(v.z, v.w);
}
__device__ __forceinline__ float redu(ull u) {
    float x, y; u2ff(u, x, y); return x + y;
}
__device__ __forceinline__ float tanhfast(float x) {
    float e = __expf(2.f * x);
    return 1.f - __fdividef(2.f, e + 1.f);
}
__device__ __forceinline__ float shflx(float v, int m) {
    return __shfl_xor_sync(0xFFFFFFFFu, v, m);
}
__device__ __forceinline__ ull shflxu(ull v, int m) {
    return __shfl_xor_sync(0xFFFFFFFFu, v, m);
}
// dot of a dense 8-float row against packed h[4]
__device__ __forceinline__ ull dot8p(const float4* row, const ull (&h)[4]) {
    ull c0, c1, c2, c3;
    ld4u(row, c0, c1);
    ld4u(row + 1, c2, c3);
    ull a = 0ull;
    a = ffma2u(c0, h[0], a);
    a = ffma2u(c1, h[1], a);
    a = ffma2u(c2, h[2], a);
    a = ffma2u(c3, h[3], a);
    return a;
}

// exchange own 4 values (packed as 2 ull) with jhalf partner -> full packed [4]
__device__ __forceinline__ void xch4(float v0, float v1, float v2, float v3,
                                     int jhalf, ull (&out)[4]) {
    ull o0 = f2u(v0, v1), o1 = f2u(v2, v3);
    ull p0 = shflxu(o0, 1), p1 = shflxu(o1, 1);
    out[0] = jhalf ? p0 : o0;
    out[1] = jhalf ? p1 : o1;
    out[2] = jhalf ? o0 : p0;
    out[3] = jhalf ? o1 : p1;
}

// ---------------- forward phase -------------------------------------------
// v[i] = t(a)[i] + v[i] * exp(s(a)[i]); role 0 computes t-net, role 1 s-net;
// jhalf owns hidden units [4h,4h+4) and output rows i === jhalf (mod 2)
__device__ __forceinline__ void fwd_phase(const float* __restrict__ sm, int ibT,
                                          const ull (&a)[16], ull (&v)[16],
                                          int role, int jhalf) {
    const int ib = ibT + role;
    const float* w0 = sm + OFF_W0 + ib * W0_STR + jhalf * 4 * W0_RSTR;
    const float* w1 = sm + OFF_W1 + ib * W1_STR + jhalf * 4 * W1_RSTR;
    const float* w2 = sm + OFF_W2 + ib * W2_STR;
    const float* b0 = sm + OFF_B0 + ib * 8 + jhalf * 4;
    const float* b1 = sm + OFF_B1 + ib * 8 + jhalf * 4;
    const float* b2 = sm + OFF_B2 + ib * B2_STR;

    // layer 0: own 4 rows, dot over all 32 inputs
    ull acc[4];
#pragma unroll
    for (int r = 0; r < 4; r++) acc[r] = 0ull;
#pragma unroll
    for (int r = 0; r < 4; r++) {
        const float4* rp = (const float4*)(w0 + r * W0_RSTR);
#pragma unroll
        for (int q = 0; q < 8; q++) {
            ull wA, wB; ld4u(rp + q, wA, wB);
            acc[r] = ffma2u(wA, a[2 * q],     acc[r]);
            acc[r] = ffma2u(wB, a[2 * q + 1], acc[r]);
        }
    }
    float h0 = tanhfast(b0[0] + redu(acc[0]));
    float h1 = tanhfast(b0[1] + redu(acc[1]));
    float h2 = tanhfast(b0[2] + redu(acc[2]));
    float h3 = tanhfast(b0[3] + redu(acc[3]));
    ull h1p[4]; xch4(h0, h1, h2, h3, jhalf, h1p);

    // layer 1: own 4 rows
    float g0 = tanhfast(b1[0] + redu(dot8p((const float4*)(w1 + 0 * W1_RSTR), h1p)));
    float g1 = tanhfast(b1[1] + redu(dot8p((const float4*)(w1 + 1 * W1_RSTR), h1p)));
    float g2 = tanhfast(b1[2] + redu(dot8p((const float4*)(w1 + 2 * W1_RSTR), h1p)));
    float g3 = tanhfast(b1[3] + redu(dot8p((const float4*)(w1 + 3 * W1_RSTR), h1p)));
    ull h2p[4]; xch4(g0, g1, g2, g3, jhalf, h2p);

    // layer 2: own 16 rows (i = 2r + jhalf), exchange t<->e^s, update v
#pragma unroll
    for (int r = 0; r < 16; r++) {
        const int i = 2 * r + jhalf;
        float val = b2[i] + redu(dot8p((const float4*)(w2 + i * 8), h2p));
        if (role) val = __expf(val);
        float other = shflx(val, 2);
        float t = role ? other : val;
        float e = role ? val : other;
        float vx, vy; u2ff(v[r], vx, vy);
        float vown = jhalf ? vy : vx;
        float vn = fmaf(vown, e, t);
        float vo = shflx(vn, 1);
        v[r] = jhalf ? f2u(vo, vn) : f2u(vn, vo);
    }
}

// ---------------- backward phase ------------------------------------------
//   u_new = (u - t(a)) * exp(-s(a))
//   yu    = (yu - (J_t + diag(u - t) J_s) yd) * exp(-s(a))
__device__ __forceinline__ void bwd_phase(const float* __restrict__ sm, int ibT,
                                          const ull (&a)[16], ull (&u)[16],
                                          const float* __restrict__ yd, float* yu,
                                          int role, int jhalf) {
    const int ib = ibT + role;
    const float* w0 = sm + OFF_W0 + ib * W0_STR + jhalf * 4 * W0_RSTR;
    const float* w1 = sm + OFF_W1 + ib * W1_STR + jhalf * 4 * W1_RSTR;
    const float* w2 = sm + OFF_W2 + ib * W2_STR;
    const float* b0 = sm + OFF_B0 + ib * 8 + jhalf * 4;
    const float* b1 = sm + OFF_B1 + ib * 8 + jhalf * 4;
    const float* b2 = sm + OFF_B2 + ib * B2_STR;

    // direction vector (full 32) from smem
    ull d[16];
    const float2* d2 = (const float2*)yd;
#pragma unroll
    for (int m = 0; m < 16; m++) d[m] = ld2u(d2 + m);

    // fused layer 0: hidden pre-acts (a) + JVP pre-acts (d), own 4 rows
    ull aH[4], aD[4];
#pragma unroll
    for (int r = 0; r < 4; r++) { aH[r] = 0ull; aD[r] = 0ull; }
#pragma unroll
    for (int r = 0; r < 4; r++) {
        const float4* rp = (const float4*)(w0 + r * W0_RSTR);
#pragma unroll
        for (int q = 0; q < 8; q++) {
            ull wA, wB; ld4u(rp + q, wA, wB);
            aH[r] = ffma2u(wA, a[2 * q],     aH[r]);
            aD[r] = ffma2u(wA, d[2 * q],     aD[r]);
            aH[r] = ffma2u(wB, a[2 * q + 1], aH[r]);
            aD[r] = ffma2u(wB, d[2 * q + 1], aD[r]);
        }
    }
    float hv[4], pv[4];
#pragma unroll
    for (int r = 0; r < 4; r++) {
        float t = tanhfast(b0[r] + redu(aH[r]));
        hv[r] = t;
        pv[r] = (1.f - t * t) * redu(aD[r]);
    }
    ull h1p[4], pp[4];
    xch4(hv[0], hv[1], hv[2], hv[3], jhalf, h1p);
    xch4(pv[0], pv[1], pv[2], pv[3], jhalf, pp);

    // fused layer 1, own 4 rows
    float gv[4], qv[4];
#pragma unroll
    for (int r = 0; r < 4; r++) {
        const float4* rp = (const float4*)(w1 + r * W1_RSTR);
        ull c0, c1, c2, c3;
        ld4u(rp,     c0, c1);
        ld4u(rp + 1, c2, c3);
        ull mH = 0ull, mQ = 0ull;
        mH = ffma2u(c0, h1p[0], mH); mQ = ffma2u(c0, pp[0], mQ);
        mH = ffma2u(c1, h1p[1], mH); mQ = ffma2u(c1, pp[1], mQ);
        mH = ffma2u(c2, h1p[2], mH); mQ = ffma2u(c2, pp[2], mQ);
        mH = ffma2u(c3, h1p[3], mH); mQ = ffma2u(c3, pp[3], mQ);
        float t = tanhfast(b1[r] + redu(mH));
        gv[r] = t;
        qv[r] = (1.f - t * t) * redu(mQ);
    }
    ull h2p[4], qp[4];
    xch4(gv[0], gv[1], gv[2], gv[3], jhalf, h2p);
    xch4(qv[0], qv[1], qv[2], qv[3], jhalf, qp);

    // layer 2: own 16 rows, exchange (t,cT)<->(e^-s,dS), inverse update
#pragma unroll
    for (int r = 0; r < 16; r++) {
        const int i = 2 * r + jhalf;
        const float4* rp = (const float4*)(w2 + i * 8);
        ull c0, c1, c2, c3;
        ld4u(rp,     c0, c1);
        ld4u(rp + 1, c2, c3);
        ull mM = 0ull, mX = 0ull;
        mM = ffma2u(c0, h2p[0], mM); mX = ffma2u(c0, qp[0], mX);
        mM = ffma2u(c1, h2p[1], mM); mX = ffma2u(c1, qp[1], mX);
        mM = ffma2u(c2, h2p[2], mM); mX = ffma2u(c2, qp[2], mX);
        mM = ffma2u(c3, h2p[3], mM); mX = ffma2u(c3, qp[3], mX);
        float rv = b2[i] + redu(mM);   // T: t_i   S: s_i
        float xv = redu(mX);           // T: cT_i  S: dS_i
        if (role) rv = __expf(-rv);    // S sends e^{-s}
        float oA = shflx(rv, 2);
        float oB = shflx(xv, 2);
        float tt = role ? oA : rv;
        float ee = role ? rv : oA;
        float cT = role ? oB : xv;
        float dS = role ? xv : oB;
        float ux, uy; u2ff(u[r], ux, uy);
        float uown = jhalf ? uy : ux;
        float dd = uown - tt;          // = u_prev * e^{s}
        float un = dd * ee;
        float cv = cT + dd * dS;       // (C * yd)_i
        if (!role) yu[i] = (yu[i] - cv) * ee;
        float uo = shflx(un, 1);
        u[r] = jhalf ? f2u(uo, un) : f2u(un, uo);
    }
}

__global__ __launch_bounds__(TPB, 1)
void nf4_kernel(const float* __restrict__ gX, const float* __restrict__ gXs,
                const float* __restrict__ gW0, const float* __restrict__ gB0,
                const float* __restrict__ gW1, const float* __restrict__ gB1,
                const float* __restrict__ gW2, const float* __restrict__ gB2,
                float* __restrict__ gOut) {
    extern __shared__ float sm[];
    const int tid = threadIdx.x;

    // cooperative weight load with skewed layout
    for (int i = tid; i < 8192; i += TPB)
        sm[OFF_W0 + (i >> 8) * W0_STR + ((i >> 5) & 7) * W0_RSTR + (i & 31)] = gW0[i];
    for (int i = tid; i < 2048; i += TPB)
        sm[OFF_W1 + (i >> 6) * W1_STR + ((i >> 3) & 7) * W1_RSTR + (i & 7)] = gW1[i];
    for (int i = tid; i < 8192; i += TPB)
        sm[OFF_W2 + (i >> 8) * W2_STR + (i & 255)] = gW2[i];
    for (int i = tid; i < 256;  i += TPB) sm[OFF_B0 + i] = gB0[i];
    for (int i = tid; i < 256;  i += TPB) sm[OFF_B1 + i] = gB1[i];
    for (int i = tid; i < 1024; i += TPB) sm[OFF_B2 + (i >> 5) * B2_STR + (i & 31)] = gB2[i];
    __syncthreads();

    const int quad   = tid & 3;
    const int jhalf  = quad & 1;
    const int role   = (quad >> 1) & 1;
    const int s_in_b = tid >> 2;
    const int samp   = blockIdx.x * SPB + s_in_b;

    const float2* xr = (const float2*)(gX + (size_t)samp * 64);
    ull lo[16], up[16];
#pragma unroll
    for (int m = 0; m < 16; m++) { lo[m] = ld2u(xr + m); up[m] = ld2u(xr + 16 + m); }

    // ---------- forward: z = phi(x) ----------
    for (int k = 0; k < NF; k++) {
        fwd_phase(sm, k * 4 + 0, lo, up, role, jhalf);   // up' = t1(lo)+up*exp(s1(lo))
        fwd_phase(sm, k * 4 + 2, up, lo, role, jhalf);   // lo' = t2(up')+lo*exp(s2(up'))
    }

    // ---------- rhs: g = -2 (x - x_star); each lane writes 16 of 64 ----------
    float* ys = sm + OFF_Y + s_in_b * Y_STRIDE;          // [0..31]=ylo, [32..63]=yup
    {
        const float* xp  = gX  + (size_t)samp * 64 + quad * 16;
        const float* xsp = gXs + (size_t)samp * 64 + quad * 16;
        float* yh = ys + quad * 16;
#pragma unroll
        for (int i = 0; i < 16; i++) yh[i] = -2.f * (xp[i] - xsp[i]);
    }
    __syncwarp();

    // ---------- backward: y <- J_k^{-1} y with exact state reconstruction ----
    for (int k = NF - 1; k >= 0; k--) {
        bwd_phase(sm, k * 4 + 2, up, lo, ys + 32, ys, role, jhalf);   // invert lo-update
        __syncwarp();
        bwd_phase(sm, k * 4 + 0, lo, up, ys, ys + 32, role, jhalf);   // invert up-update
        __syncwarp();
    }

    // ---------- output: each lane writes its 16 ----------
    float* op = gOut + (size_t)samp * 64 + quad * 16;
    const float* yh = ys + quad * 16;
#pragma unroll
    for (int i = 0; i < 16; i++) op[i] = yh[i];
}

extern "C" void kernel_launch(void* const* d_in, const int* in_sizes, int n_in,
                              void* d_out, int out_size) {
    const float* x  = (const float*)d_in[0];
    const float* xs = (const float*)d_in[1];
    const float* W0 = (const float*)d_in[2];
    const float* b0 = (const float*)d_in[3];
    const float* W1 = (const float*)d_in[4];
    const float* b1 = (const float*)d_in[5];
    const float* W2 = (const float*)d_in[6];
    const float* b2 = (const float*)d_in[7];
    float* out = (float*)d_out;

    cudaFuncSetAttribute(nf4_kernel, cudaFuncAttributeMaxDynamicSharedMemorySize, SMEM_BYTES);
    nf4_kernel<<<(BSZ * 4) / TPB, TPB, SMEM_BYTES>>>(x, xs, W0, b0, W1, b1, W2, b2, out);
}

// round 9
// speedup vs baseline: 1.8494x; 1.1600x over previous
#include <cuda_runtime.h>
#include <cuda_bf16.h>

typedef unsigned long long ull;

#define BSZ   16384
#define NF    8
#define TPB   256          // 64 sample-slots/block × 4 lanes; 2 samples/thread
#define SLOTS (TPB / 4)    // 64
#define SPB   (SLOTS * 2)  // 128 samples per block

// skewed smem weight layout (float offsets)
#define W0_RSTR 36
#define W0_STR  296
#define W1_RSTR 12
#define W1_STR  104
#define W2_STR  272
#define B2_STR  36

#define OFF_W0 0
#define OFF_W1 9472
#define OFF_W2 12800
#define OFF_B0 21504
#define OFF_B1 21760
#define OFF_B2 22016
#define OFF_Y  23168
#define Y_STRIDE 68        // 272B: 16B-aligned, 17-bank rotation per slot
#define SMEM_FLOATS (OFF_Y + SPB * Y_STRIDE)
#define SMEM_BYTES  (SMEM_FLOATS * 4)

// ---------------- packed f32x2 helpers ----------------
__device__ __forceinline__ ull ffma2u(ull a, ull b, ull c) {
    asm("fma.rn.f32x2 %0, %1, %2, %0;" : "+l"(c) : "l"(a), "l"(b));
    return c;
}
__device__ __forceinline__ ull f2u(float x, float y) {
    ull u; asm("mov.b64 %0, {%1, %2};" : "=l"(u) : "f"(x), "f"(y)); return u;
}
__device__ __forceinline__ void u2ff(ull u, float& x, float& y) {
    asm("mov.b64 {%0, %1}, %2;" : "=f"(x), "=f"(y) : "l"(u));
}
__device__ __forceinline__ ull ld2u(const float2* p) {
    float2 v = *p; return f2u(v.x, v.y);
}
__device__ __forceinline__ void ld4u(const float4* p, ull& u0, ull& u1) {
    float4 v = *p; u0 = f2u(v.x, v.y); u1 = f2u(v.z, v.w);
}
__device__ __forceinline__ float redu(ull u) {
    float x, y; u2ff(u, x, y); return x + y;
}
__device__ __forceinline__ float tanhfast(float x) {
    float e = __expf(2.f * x);
    return 1.f - __fdividef(2.f, e + 1.f);
}
__device__ __forceinline__ float shflx(float v, int m) {
    return __shfl_xor_sync(0xFFFFFFFFu, v, m);
}
__device__ __forceinline__ ull shflxu(ull v, int m) {
    return __shfl_xor_sync(0xFFFFFFFFu, v, m);
}
// exchange own 4 values with jhalf partner -> full packed [4]
__device__ __forceinline__ void xch4(float v0, float v1, float v2, float v3,
                                     int jhalf, ull (&out)[4]) {
    ull o0 = f2u(v0, v1), o1 = f2u(v2, v3);
    ull p0 = shflxu(o0, 1), p1 = shflxu(o1, 1);
    out[0] = jhalf ? p0 : o0;
    out[1] = jhalf ? p1 : o1;
    out[2] = jhalf ? o0 : p0;
    out[3] = jhalf ? o1 : p1;
}

// ---------------- forward phase, 2 samples per thread ---------------------
// v[i] = t(a)[i] + v[i]*exp(s(a)[i]); role 0 = t-net, 1 = s-net;
// jhalf owns hidden units [4h,4h+4) and output rows i === jhalf (mod 2)
__device__ __forceinline__ void fwd_phase2(const float* __restrict__ sm, int ibT,
                                           const ull (&a)[2][16], ull (&v)[2][16],
                                           int role, int jhalf) {
    const int ib = ibT + role;
    const float* w0 = sm + OFF_W0 + ib * W0_STR + jhalf * 4 * W0_RSTR;
    const float* w1 = sm + OFF_W1 + ib * W1_STR + jhalf * 4 * W1_RSTR;
    const float* w2 = sm + OFF_W2 + ib * W2_STR;
    const float* b0 = sm + OFF_B0 + ib * 8 + jhalf * 4;
    const float* b1 = sm + OFF_B1 + ib * 8 + jhalf * 4;
    const float* b2 = sm + OFF_B2 + ib * B2_STR;

    // layer 0: own 4 rows over all 32 inputs, weights shared across samples
    ull acc[2][4];
#pragma unroll
    for (int r = 0; r < 4; r++) { acc[0][r] = 0ull; acc[1][r] = 0ull; }
#pragma unroll
    for (int r = 0; r < 4; r++) {
        const float4* rp = (const float4*)(w0 + r * W0_RSTR);
#pragma unroll
        for (int q = 0; q < 8; q++) {
            ull wA, wB; ld4u(rp + q, wA, wB);
            acc[0][r] = ffma2u(wA, a[0][2 * q],     acc[0][r]);
            acc[0][r] = ffma2u(wB, a[0][2 * q + 1], acc[0][r]);
            acc[1][r] = ffma2u(wA, a[1][2 * q],     acc[1][r]);
            acc[1][r] = ffma2u(wB, a[1][2 * q + 1], acc[1][r]);
        }
    }
    ull h1p[2][4];
#pragma unroll
    for (int si = 0; si < 2; si++) {
        float h0 = tanhfast(b0[0] + redu(acc[si][0]));
        float h1 = tanhfast(b0[1] + redu(acc[si][1]));
        float h2 = tanhfast(b0[2] + redu(acc[si][2]));
        float h3 = tanhfast(b0[3] + redu(acc[si][3]));
        xch4(h0, h1, h2, h3, jhalf, h1p[si]);
    }

    // layer 1: own 4 rows, row loaded once for both samples
    float g[2][4];
#pragma unroll
    for (int r = 0; r < 4; r++) {
        const float4* rp = (const float4*)(w1 + r * W1_RSTR);
        ull c0, c1, c2, c3;
        ld4u(rp,     c0, c1);
        ld4u(rp + 1, c2, c3);
#pragma unroll
        for (int si = 0; si < 2; si++) {
            ull m = 0ull;
            m = ffma2u(c0, h1p[si][0], m);
            m = ffma2u(c1, h1p[si][1], m);
            m = ffma2u(c2, h1p[si][2], m);
            m = ffma2u(c3, h1p[si][3], m);
            g[si][r] = tanhfast(b1[r] + redu(m));
        }
    }
    ull h2p[2][4];
    xch4(g[0][0], g[0][1], g[0][2], g[0][3], jhalf, h2p[0]);
    xch4(g[1][0], g[1][1], g[1][2], g[1][3], jhalf, h2p[1]);

    // layer 2: own 16 rows (i = 2r + jhalf), exchange t<->e^s, update v
#pragma unroll
    for (int r = 0; r < 16; r++) {
        const int i = 2 * r + jhalf;
        const float4* rp = (const float4*)(w2 + i * 8);
        ull c0, c1, c2, c3;
        ld4u(rp,     c0, c1);
        ld4u(rp + 1, c2, c3);
#pragma unroll
        for (int si = 0; si < 2; si++) {
            ull m = 0ull;
            m = ffma2u(c0, h2p[si][0], m);
            m = ffma2u(c1, h2p[si][1], m);
            m = ffma2u(c2, h2p[si][2], m);
            m = ffma2u(c3, h2p[si][3], m);
            float val = b2[i] + redu(m);
            if (role) val = __expf(val);
            float other = shflx(val, 2);
            float t = role ? other : val;
            float e = role ? val : other;
            float vx, vy; u2ff(v[si][r], vx, vy);
            float vown = jhalf ? vy : vx;
            float vn = fmaf(vown, e, t);
            float vo = shflx(vn, 1);
            v[si][r] = jhalf ? f2u(vo, vn) : f2u(vn, vo);
        }
    }
}

// ---------------- backward phase, 2 samples per thread --------------------
//   u_new = (u - t(a)) * exp(-s(a))
//   yu    = (yu - (J_t + diag(u - t) J_s) yd) * exp(-s(a))
__device__ __forceinline__ void bwd_phase2(const float* __restrict__ sm, int ibT,
                                           const ull (&a)[2][16], ull (&u)[2][16],
                                           const float* __restrict__ yd0,
                                           const float* __restrict__ yd1,
                                           float* yu0, float* yu1,
                                           int role, int jhalf) {
    const int ib = ibT + role;
    const float* w0 = sm + OFF_W0 + ib * W0_STR + jhalf * 4 * W0_RSTR;
    const float* w1 = sm + OFF_W1 + ib * W1_STR + jhalf * 4 * W1_RSTR;
    const float* w2 = sm + OFF_W2 + ib * W2_STR;
    const float* b0 = sm + OFF_B0 + ib * 8 + jhalf * 4;
    const float* b1 = sm + OFF_B1 + ib * 8 + jhalf * 4;
    const float* b2 = sm + OFF_B2 + ib * B2_STR;

    // fused layer 0: hidden pre-acts (a) + JVP pre-acts (d); q-outer so the
    // direction streams from smem via LDS.128 with no register cache
    ull aH[2][4], aD[2][4];
#pragma unroll
    for (int r = 0; r < 4; r++) {
        aH[0][r] = 0ull; aD[0][r] = 0ull;
        aH[1][r] = 0ull; aD[1][r] = 0ull;
    }
    const float4* yd0v = (const float4*)yd0;
    const float4* yd1v = (const float4*)yd1;
#pragma unroll
    for (int q = 0; q < 8; q++) {
        ull d00, d01, d10, d11;
        ld4u(yd0v + q, d00, d01);
        ld4u(yd1v + q, d10, d11);
        ull a00 = a[0][2 * q], a01 = a[0][2 * q + 1];
        ull a10 = a[1][2 * q], a11 = a[1][2 * q + 1];
#pragma unroll
        for (int r = 0; r < 4; r++) {
            ull wA, wB;
            ld4u((const float4*)(w0 + r * W0_RSTR) + q, wA, wB);
            aH[0][r] = ffma2u(wA, a00, aH[0][r]);
            aD[0][r] = ffma2u(wA, d00, aD[0][r]);
            aH[0][r] = ffma2u(wB, a01, aH[0][r]);
            aD[0][r] = ffma2u(wB, d01, aD[0][r]);
            aH[1][r] = ffma2u(wA, a10, aH[1][r]);
            aD[1][r] = ffma2u(wA, d10, aD[1][r]);
            aH[1][r] = ffma2u(wB, a11, aH[1][r]);
            aD[1][r] = ffma2u(wB, d11, aD[1][r]);
        }
    }
    ull h1p[2][4], pp[2][4];
#pragma unroll
    for (int si = 0; si < 2; si++) {
        float hv[4], pv[4];
#pragma unroll
        for (int r = 0; r < 4; r++) {
            float t = tanhfast(b0[r] + redu(aH[si][r]));
            hv[r] = t;
            pv[r] = (1.f - t * t) * redu(aD[si][r]);
        }
        xch4(hv[0], hv[1], hv[2], hv[3], jhalf, h1p[si]);
        xch4(pv[0], pv[1], pv[2], pv[3], jhalf, pp[si]);
    }

    // fused layer 1: row loaded once, 4 accumulators (H,Q × 2 samples)
    float gv[2][4], qv[2][4];
#pragma unroll
    for (int r = 0; r < 4; r++) {
        const float4* rp = (const float4*)(w1 + r * W1_RSTR);
        ull c0, c1, c2, c3;
        ld4u(rp,     c0, c1);
        ld4u(rp + 1, c2, c3);
#pragma unroll
        for (int si = 0; si < 2; si++) {
            ull mH = 0ull, mQ = 0ull;
            mH = ffma2u(c0, h1p[si][0], mH); mQ = ffma2u(c0, pp[si][0], mQ);
            mH = ffma2u(c1, h1p[si][1], mH); mQ = ffma2u(c1, pp[si][1], mQ);
            mH = ffma2u(c2, h1p[si][2], mH); mQ = ffma2u(c2, pp[si][2], mQ);
            mH = ffma2u(c3, h1p[si][3], mH); mQ = ffma2u(c3, pp[si][3], mQ);
            float t = tanhfast(b1[r] + redu(mH));
            gv[si][r] = t;
            qv[si][r] = (1.f - t * t) * redu(mQ);
        }
    }
    ull h2p[2][4], qp[2][4];
#pragma unroll
    for (int si = 0; si < 2; si++) {
        xch4(gv[si][0], gv[si][1], gv[si][2], gv[si][3], jhalf, h2p[si]);
        xch4(qv[si][0], qv[si][1], qv[si][2], qv[si][3], jhalf, qp[si]);
    }

    // layer 2: own 16 rows, exchange (t,cT)<->(e^-s,dS), inverse update
#pragma unroll
    for (int r = 0; r < 16; r++) {
        const int i = 2 * r + jhalf;
        const float4* rp = (const float4*)(w2 + i * 8);
        ull c0, c1, c2, c3;
        ld4u(rp,     c0, c1);
        ld4u(rp + 1, c2, c3);
#pragma unroll
        for (int si = 0; si < 2; si++) {
            ull mM = 0ull, mX = 0ull;
            mM = ffma2u(c0, h2p[si][0], mM); mX = ffma2u(c0, qp[si][0], mX);
            mM = ffma2u(c1, h2p[si][1], mM); mX = ffma2u(c1, qp[si][1], mX);
            mM = ffma2u(c2, h2p[si][2], mM); mX = ffma2u(c2, qp[si][2], mX);
            mM = ffma2u(c3, h2p[si][3], mM); mX = ffma2u(c3, qp[si][3], mX);
            float rv = b2[i] + redu(mM);   // T: t_i   S: s_i
            float xv = redu(mX);           // T: cT_i  S: dS_i
            if (role) rv = __expf(-rv);    // S sends e^{-s}
            float oA = shflx(rv, 2);
            float oB = shflx(xv, 2);
            float tt = role ? oA : rv;
            float ee = role ? rv : oA;
            float cT = role ? oB : xv;
            float dS = role ? xv : oB;
            float ux, uy; u2ff(u[si][r], ux, uy);
            float uown = jhalf ? uy : ux;
            float dd = uown - tt;          // = u_prev * e^{s}
            float un = dd * ee;
            float cv = cT + dd * dS;       // (C * yd)_i
            if (!role) {
                float* yu = si ? yu1 : yu0;
                yu[i] = (yu[i] - cv) * ee;
            }
            float uo = shflx(un, 1);
            u[si][r] = jhalf ? f2u(uo, un) : f2u(un, uo);
        }
    }
}

__global__ __launch_bounds__(TPB, 1)
void nf5_kernel(const float* __restrict__ gX, const float* __restrict__ gXs,
                const float* __restrict__ gW0, const float* __restrict__ gB0,
                const float* __restrict__ gW1, const float* __restrict__ gB1,
                const float* __restrict__ gW2, const float* __restrict__ gB2,
                float* __restrict__ gOut) {
    extern __shared__ float sm[];
    const int tid = threadIdx.x;

    // cooperative weight load with skewed layout
    for (int i = tid; i < 8192; i += TPB)
        sm[OFF_W0 + (i >> 8) * W0_STR + ((i >> 5) & 7) * W0_RSTR + (i & 31)] = gW0[i];
    for (int i = tid; i < 2048; i += TPB)
        sm[OFF_W1 + (i >> 6) * W1_STR + ((i >> 3) & 7) * W1_RSTR + (i & 7)] = gW1[i];
    for (int i = tid; i < 8192; i += TPB)
        sm[OFF_W2 + (i >> 8) * W2_STR + (i & 255)] = gW2[i];
    for (int i = tid; i < 256;  i += TPB) sm[OFF_B0 + i] = gB0[i];
    for (int i = tid; i < 256;  i += TPB) sm[OFF_B1 + i] = gB1[i];
    for (int i = tid; i < 1024; i += TPB) sm[OFF_B2 + (i >> 5) * B2_STR + (i & 31)] = gB2[i];
    __syncthreads();

    const int quad   = tid & 3;
    const int jhalf  = quad & 1;
    const int role   = (quad >> 1) & 1;
    const int slot   = tid >> 2;                 // 0..63
    const int samp0  = blockIdx.x * SPB + slot;  // this thread's two samples
    const int samp1  = samp0 + SLOTS;

    ull lo[2][16], up[2][16];
    {
        const float2* x0 = (const float2*)(gX + (size_t)samp0 * 64);
        const float2* x1 = (const float2*)(gX + (size_t)samp1 * 64);
#pragma unroll
        for (int m = 0; m < 16; m++) {
            lo[0][m] = ld2u(x0 + m); up[0][m] = ld2u(x0 + 16 + m);
            lo[1][m] = ld2u(x1 + m); up[1][m] = ld2u(x1 + 16 + m);
        }
    }

    // ---------- forward: z = phi(x) ----------
    for (int k = 0; k < NF; k++) {
        fwd_phase2(sm, k * 4 + 0, lo, up, role, jhalf);
        fwd_phase2(sm, k * 4 + 2, up, lo, role, jhalf);
    }

    // ---------- rhs: g = -2 (x - x_star); each lane writes its 16 per sample ----
    float* ys0 = sm + OFF_Y + slot * Y_STRIDE;
    float* ys1 = sm + OFF_Y + (slot + SLOTS) * Y_STRIDE;
#pragma unroll
    for (int si = 0; si < 2; si++) {
        const int samp = si ? samp1 : samp0;
        const float* xp  = gX  + (size_t)samp * 64 + quad * 16;
        const float* xsp = gXs + (size_t)samp * 64 + quad * 16;
        float* yh = (si ? ys1 : ys0) + quad * 16;
#pragma unroll
        for (int i = 0; i < 16; i++) yh[i] = -2.f * (xp[i] - xsp[i]);
    }
    __syncwarp();

    // ---------- backward: y <- J_k^{-1} y with exact state reconstruction ----
    for (int k = NF - 1; k >= 0; k--) {
        bwd_phase2(sm, k * 4 + 2, up, lo, ys0 + 32, ys1 + 32, ys0, ys1, role, jhalf);
        __syncwarp();
        bwd_phase2(sm, k * 4 + 0, lo, up, ys0, ys1, ys0 + 32, ys1 + 32, role, jhalf);
        __syncwarp();
    }

    // ---------- output ----------
#pragma unroll
    for (int si = 0; si < 2; si++) {
        const int samp = si ? samp1 : samp0;
        float* op = gOut + (size_t)samp * 64 + quad * 16;
        const float* yh = (si ? ys1 : ys0) + quad * 16;
#pragma unroll
        for (int i = 0; i < 16; i++) op[i] = yh[i];
    }
}

extern "C" void kernel_launch(void* const* d_in, const int* in_sizes, int n_in,
                              void* d_out, int out_size) {
    const float* x  = (const float*)d_in[0];
    const float* xs = (const float*)d_in[1];
    const float* W0 = (const float*)d_in[2];
    const float* b0 = (const float*)d_in[3];
    const float* W1 = (const float*)d_in[4];
    const float* b1 = (const float*)d_in[5];
    const float* W2 = (const float*)d_in[6];
    const float* b2 = (const float*)d_in[7];
    float* out = (float*)d_out;

    cudaFuncSetAttribute(nf5_kernel, cudaFuncAttributeMaxDynamicSharedMemorySize, SMEM_BYTES);
    nf5_kernel<<<BSZ / SPB, TPB, SMEM_BYTES>>>(x, xs, W0, b0, W1, b1, W2, b2, out);
}

// round 10
// speedup vs baseline: 1.9987x; 1.0807x over previous
#include <cuda_runtime.h>
#include <cuda_bf16.h>

typedef unsigned long long ull;

#define BSZ   16384
#define NF    8
#define TPB   256          // 64 sample-slots/block × 4 lanes; 2 samples/thread
#define SLOTS (TPB / 4)    // 64
#define SPB   (SLOTS * 2)  // 128 samples per block

// skewed smem weight layout (float offsets)
#define W0_RSTR 36
#define W0_STR  296
#define W1_RSTR 12
#define W1_STR  104
#define W2_STR  272
#define B2_STR  36

#define OFF_W0 0
#define OFF_W1 9472
#define OFF_W2 12800
#define OFF_B0 21504
#define OFF_B1 21760
#define OFF_B2 22016
#define OFF_Y  23168
#define Y_STRIDE 68        // 272B: 16B-aligned, 17-bank rotation per slot
#define SMEM_FLOATS (OFF_Y + SPB * Y_STRIDE)
#define SMEM_BYTES  (SMEM_FLOATS * 4)

// ---------------- packed f32x2 helpers ----------------
__device__ __forceinline__ ull ffma2u(ull a, ull b, ull c) {
    asm("fma.rn.f32x2 %0, %1, %2, %0;" : "+l"(c) : "l"(a), "l"(b));
    return c;
}
__device__ __forceinline__ ull f2u(float x, float y) {
    ull u; asm("mov.b64 %0, {%1, %2};" : "=l"(u) : "f"(x), "f"(y)); return u;
}
__device__ __forceinline__ void u2ff(ull u, float& x, float& y) {
    asm("mov.b64 {%0, %1}, %2;" : "=f"(x), "=f"(y) : "l"(u));
}
__device__ __forceinline__ ull ld2u(const float2* p) {
    float2 v = *p; return f2u(v.x, v.y);
}
__device__ __forceinline__ void ld4u(const float4* p, ull& u0, ull& u1) {
    float4 v = *p; u0 = f2u(v.x, v.y); u1 = f2u(v.z, v.w);
}
__device__ __forceinline__ float redu(ull u) {
    float x, y; u2ff(u, x, y); return x + y;
}
// single-MUFU tanh (sm_75+); bwd recomputes identical values so the
// flow inversion stays exact; only Jacobian entries carry ~5e-4 approx error
__device__ __forceinline__ float tanhfast(float x) {
    float r; asm("tanh.approx.f32 %0, %1;" : "=f"(r) : "f"(x));
    return r;
}
__device__ __forceinline__ float shflx(float v, int m) {
    return __shfl_xor_sync(0xFFFFFFFFu, v, m);
}
__device__ __forceinline__ ull shflxu(ull v, int m) {
    return __shfl_xor_sync(0xFFFFFFFFu, v, m);
}
// exchange own 4 values with jhalf partner -> full packed [4]
__device__ __forceinline__ void xch4(float v0, float v1, float v2, float v3,
                                     int jhalf, ull (&out)[4]) {
    ull o0 = f2u(v0, v1), o1 = f2u(v2, v3);
    ull p0 = shflxu(o0, 1), p1 = shflxu(o1, 1);
    out[0] = jhalf ? p0 : o0;
    out[1] = jhalf ? p1 : o1;
    out[2] = jhalf ? o0 : p0;
    out[3] = jhalf ? o1 : p1;
}

// ---------------- forward phase, 2 samples per thread ---------------------
// v[i] = t(a)[i] + v[i]*exp(s(a)[i]); role 0 = t-net, 1 = s-net;
// jhalf owns hidden units [4h,4h+4) and output rows i === jhalf (mod 2)
__device__ __forceinline__ void fwd_phase2(const float* __restrict__ sm, int ibT,
                                           const ull (&a)[2][16], ull (&v)[2][16],
                                           int role, int jhalf) {
    const int ib = ibT + role;
    const float* w0 = sm + OFF_W0 + ib * W0_STR + jhalf * 4 * W0_RSTR;
    const float* w1 = sm + OFF_W1 + ib * W1_STR + jhalf * 4 * W1_RSTR;
    const float* w2 = sm + OFF_W2 + ib * W2_STR;
    const float* b0 = sm + OFF_B0 + ib * 8 + jhalf * 4;
    const float* b1 = sm + OFF_B1 + ib * 8 + jhalf * 4;
    const float* b2 = sm + OFF_B2 + ib * B2_STR;

    // layer 0: own 4 rows over all 32 inputs, weights shared across samples
    ull acc[2][4];
#pragma unroll
    for (int r = 0; r < 4; r++) { acc[0][r] = 0ull; acc[1][r] = 0ull; }
#pragma unroll
    for (int r = 0; r < 4; r++) {
        const float4* rp = (const float4*)(w0 + r * W0_RSTR);
#pragma unroll
        for (int q = 0; q < 8; q++) {
            ull wA, wB; ld4u(rp + q, wA, wB);
            acc[0][r] = ffma2u(wA, a[0][2 * q],     acc[0][r]);
            acc[0][r] = ffma2u(wB, a[0][2 * q + 1], acc[0][r]);
            acc[1][r] = ffma2u(wA, a[1][2 * q],     acc[1][r]);
            acc[1][r] = ffma2u(wB, a[1][2 * q + 1], acc[1][r]);
        }
    }
    ull h1p[2][4];
#pragma unroll
    for (int si = 0; si < 2; si++) {
        float h0 = tanhfast(b0[0] + redu(acc[si][0]));
        float h1 = tanhfast(b0[1] + redu(acc[si][1]));
        float h2 = tanhfast(b0[2] + redu(acc[si][2]));
        float h3 = tanhfast(b0[3] + redu(acc[si][3]));
        xch4(h0, h1, h2, h3, jhalf, h1p[si]);
    }

    // layer 1: own 4 rows, row loaded once for both samples
    float g[2][4];
#pragma unroll
    for (int r = 0; r < 4; r++) {
        const float4* rp = (const float4*)(w1 + r * W1_RSTR);
        ull c0, c1, c2, c3;
        ld4u(rp,     c0, c1);
        ld4u(rp + 1, c2, c3);
#pragma unroll
        for (int si = 0; si < 2; si++) {
            ull m = 0ull;
            m = ffma2u(c0, h1p[si][0], m);
            m = ffma2u(c1, h1p[si][1], m);
            m = ffma2u(c2, h1p[si][2], m);
            m = ffma2u(c3, h1p[si][3], m);
            g[si][r] = tanhfast(b1[r] + redu(m));
        }
    }
    ull h2p[2][4];
    xch4(g[0][0], g[0][1], g[0][2], g[0][3], jhalf, h2p[0]);
    xch4(g[1][0], g[1][1], g[1][2], g[1][3], jhalf, h2p[1]);

    // layer 2: own 16 rows (i = 2r + jhalf), exchange t<->e^s, update v
#pragma unroll
    for (int r = 0; r < 16; r++) {
        const int i = 2 * r + jhalf;
        const float4* rp = (const float4*)(w2 + i * 8);
        ull c0, c1, c2, c3;
        ld4u(rp,     c0, c1);
        ld4u(rp + 1, c2, c3);
#pragma unroll
        for (int si = 0; si < 2; si++) {
            ull m = 0ull;
            m = ffma2u(c0, h2p[si][0], m);
            m = ffma2u(c1, h2p[si][1], m);
            m = ffma2u(c2, h2p[si][2], m);
            m = ffma2u(c3, h2p[si][3], m);
            float val = b2[i] + redu(m);
            if (role) val = __expf(val);
            float other = shflx(val, 2);
            float t = role ? other : val;
            float e = role ? val : other;
            float vx, vy; u2ff(v[si][r], vx, vy);
            float vown = jhalf ? vy : vx;
            float vn = fmaf(vown, e, t);
            float vo = shflx(vn, 1);
            v[si][r] = jhalf ? f2u(vo, vn) : f2u(vn, vo);
        }
    }
}

// ---------------- backward phase, 2 samples per thread --------------------
//   u_new = (u - t(a)) * exp(-s(a))
//   yu    = (yu - (J_t + diag(u - t) J_s) yd) * exp(-s(a))
__device__ __forceinline__ void bwd_phase2(const float* __restrict__ sm, int ibT,
                                           const ull (&a)[2][16], ull (&u)[2][16],
                                           const float* __restrict__ yd0,
                                           const float* __restrict__ yd1,
                                           float* yu0, float* yu1,
                                           int role, int jhalf) {
    const int ib = ibT + role;
    const float* w0 = sm + OFF_W0 + ib * W0_STR + jhalf * 4 * W0_RSTR;
    const float* w1 = sm + OFF_W1 + ib * W1_STR + jhalf * 4 * W1_RSTR;
    const float* w2 = sm + OFF_W2 + ib * W2_STR;
    const float* b0 = sm + OFF_B0 + ib * 8 + jhalf * 4;
    const float* b1 = sm + OFF_B1 + ib * 8 + jhalf * 4;
    const float* b2 = sm + OFF_B2 + ib * B2_STR;

    // fused layer 0: hidden pre-acts (a) + JVP pre-acts (d); q-outer so the
    // direction streams from smem via LDS.128 with no register cache
    ull aH[2][4], aD[2][4];
#pragma unroll
    for (int r = 0; r < 4; r++) {
        aH[0][r] = 0ull; aD[0][r] = 0ull;
        aH[1][r] = 0ull; aD[1][r] = 0ull;
    }
    const float4* yd0v = (const float4*)yd0;
    const float4* yd1v = (const float4*)yd1;
#pragma unroll
    for (int q = 0; q < 8; q++) {
        ull d00, d01, d10, d11;
        ld4u(yd0v + q, d00, d01);
        ld4u(yd1v + q, d10, d11);
        ull a00 = a[0][2 * q], a01 = a[0][2 * q + 1];
        ull a10 = a[1][2 * q], a11 = a[1][2 * q + 1];
#pragma unroll
        for (int r = 0; r < 4; r++) {
            ull wA, wB;
            ld4u((const float4*)(w0 + r * W0_RSTR) + q, wA, wB);
            aH[0][r] = ffma2u(wA, a00, aH[0][r]);
            aD[0][r] = ffma2u(wA, d00, aD[0][r]);
            aH[0][r] = ffma2u(wB, a01, aH[0][r]);
            aD[0][r] = ffma2u(wB, d01, aD[0][r]);
            aH[1][r] = ffma2u(wA, a10, aH[1][r]);
            aD[1][r] = ffma2u(wA, d10, aD[1][r]);
            aH[1][r] = ffma2u(wB, a11, aH[1][r]);
            aD[1][r] = ffma2u(wB, d11, aD[1][r]);
        }
    }
    ull h1p[2][4], pp[2][4];
#pragma unroll
    for (int si = 0; si < 2; si++) {
        float hv[4], pv[4];
#pragma unroll
        for (int r = 0; r < 4; r++) {
            float t = tanhfast(b0[r] + redu(aH[si][r]));
            hv[r] = t;
            pv[r] = (1.f - t * t) * redu(aD[si][r]);
        }
        xch4(hv[0], hv[1], hv[2], hv[3], jhalf, h1p[si]);
        xch4(pv[0], pv[1], pv[2], pv[3], jhalf, pp[si]);
    }

    // fused layer 1: row loaded once, 4 accumulators (H,Q × 2 samples)
    float gv[2][4], qv[2][4];
#pragma unroll
    for (int r = 0; r < 4; r++) {
        const float4* rp = (const float4*)(w1 + r * W1_RSTR);
        ull c0, c1, c2, c3;
        ld4u(rp,     c0, c1);
        ld4u(rp + 1, c2, c3);
#pragma unroll
        for (int si = 0; si < 2; si++) {
            ull mH = 0ull, mQ = 0ull;
            mH = ffma2u(c0, h1p[si][0], mH); mQ = ffma2u(c0, pp[si][0], mQ);
            mH = ffma2u(c1, h1p[si][1], mH); mQ = ffma2u(c1, pp[si][1], mQ);
            mH = ffma2u(c2, h1p[si][2], mH); mQ = ffma2u(c2, pp[si][2], mQ);
            mH = ffma2u(c3, h1p[si][3], mH); mQ = ffma2u(c3, pp[si][3], mQ);
            float t = tanhfast(b1[r] + redu(mH));
            gv[si][r] = t;
            qv[si][r] = (1.f - t * t) * redu(mQ);
        }
    }
    ull h2p[2][4], qp[2][4];
#pragma unroll
    for (int si = 0; si < 2; si++) {
        xch4(gv[si][0], gv[si][1], gv[si][2], gv[si][3], jhalf, h2p[si]);
        xch4(qv[si][0], qv[si][1], qv[si][2], qv[si][3], jhalf, qp[si]);
    }

    // layer 2: own 16 rows, exchange (t,cT)<->(e^-s,dS), inverse update
#pragma unroll
    for (int r = 0; r < 16; r++) {
        const int i = 2 * r + jhalf;
        const float4* rp = (const float4*)(w2 + i * 8);
        ull c0, c1, c2, c3;
        ld4u(rp,     c0, c1);
        ld4u(rp + 1, c2, c3);
#pragma unroll
        for (int si = 0; si < 2; si++) {
            ull mM = 0ull, mX = 0ull;
            mM = ffma2u(c0, h2p[si][0], mM); mX = ffma2u(c0, qp[si][0], mX);
            mM = ffma2u(c1, h2p[si][1], mM); mX = ffma2u(c1, qp[si][1], mX);
            mM = ffma2u(c2, h2p[si][2], mM); mX = ffma2u(c2, qp[si][2], mX);
            mM = ffma2u(c3, h2p[si][3], mM); mX = ffma2u(c3, qp[si][3], mX);
            float rv = b2[i] + redu(mM);   // T: t_i   S: s_i
            float xv = redu(mX);           // T: cT_i  S: dS_i
            if (role) rv = __expf(-rv);    // S sends e^{-s}
            float oA = shflx(rv, 2);
            float oB = shflx(xv, 2);
            float tt = role ? oA : rv;
            float ee = role ? rv : oA;
            float cT = role ? oB : xv;
            float dS = role ? xv : oB;
            float ux, uy; u2ff(u[si][r], ux, uy);
            float uown = jhalf ? uy : ux;
            float dd = uown - tt;          // = u_prev * e^{s}
            float un = dd * ee;
            float cv = cT + dd * dS;       // (C * yd)_i
            if (!role) {
                float* yu = si ? yu1 : yu0;
                yu[i] = (yu[i] - cv) * ee;
            }
            float uo = shflx(un, 1);
            u[si][r] = jhalf ? f2u(uo, un) : f2u(un, uo);
        }
    }
}

__global__ __launch_bounds__(TPB, 1)
void nf6_kernel(const float* __restrict__ gX, const float* __restrict__ gXs,
                const float* __restrict__ gW0, const float* __restrict__ gB0,
                const float* __restrict__ gW1, const float* __restrict__ gB1,
                const float* __restrict__ gW2, const float* __restrict__ gB2,
                float* __restrict__ gOut) {
    extern __shared__ float sm[];
    const int tid = threadIdx.x;

    // cooperative weight load with skewed layout
    for (int i = tid; i < 8192; i += TPB)
        sm[OFF_W0 + (i >> 8) * W0_STR + ((i >> 5) & 7) * W0_RSTR + (i & 31)] = gW0[i];
    for (int i = tid; i < 2048; i += TPB)
        sm[OFF_W1 + (i >> 6) * W1_STR + ((i >> 3) & 7) * W1_RSTR + (i & 7)] = gW1[i];
    for (int i = tid; i < 8192; i += TPB)
        sm[OFF_W2 + (i >> 8) * W2_STR + (i & 255)] = gW2[i];
    for (int i = tid; i < 256;  i += TPB) sm[OFF_B0 + i] = gB0[i];
    for (int i = tid; i < 256;  i += TPB) sm[OFF_B1 + i] = gB1[i];
    for (int i = tid; i < 1024; i += TPB) sm[OFF_B2 + (i >> 5) * B2_STR + (i & 31)] = gB2[i];
    __syncthreads();

    const int quad   = tid & 3;
    const int jhalf  = quad & 1;
    const int role   = (quad >> 1) & 1;
    const int slot   = tid >> 2;                 // 0..63
    const int samp0  = blockIdx.x * SPB + slot;  // this thread's two samples
    const int samp1  = samp0 + SLOTS;

    ull lo[2][16], up[2][16];
    {
        const float2* x0 = (const float2*)(gX + (size_t)samp0 * 64);
        const float2* x1 = (const float2*)(gX + (size_t)samp1 * 64);
#pragma unroll
        for (int m = 0; m < 16; m++) {
            lo[0][m] = ld2u(x0 + m); up[0][m] = ld2u(x0 + 16 + m);
            lo[1][m] = ld2u(x1 + m); up[1][m] = ld2u(x1 + 16 + m);
        }
    }

    // ---------- forward: z = phi(x) ----------
    for (int k = 0; k < NF; k++) {
        fwd_phase2(sm, k * 4 + 0, lo, up, role, jhalf);
        fwd_phase2(sm, k * 4 + 2, up, lo, role, jhalf);
    }

    // ---------- rhs: g = -2 (x - x_star); each lane writes its 16 per sample ----
    float* ys0 = sm + OFF_Y + slot * Y_STRIDE;
    float* ys1 = sm + OFF_Y + (slot + SLOTS) * Y_STRIDE;
#pragma unroll
    for (int si = 0; si < 2; si++) {
        const int samp = si ? samp1 : samp0;
        const float* xp  = gX  + (size_t)samp * 64 + quad * 16;
        const float* xsp = gXs + (size_t)samp * 64 + quad * 16;
        float* yh = (si ? ys1 : ys0) + quad * 16;
#pragma unroll
        for (int i = 0; i < 16; i++) yh[i] = -2.f * (xp[i] - xsp[i]);
    }
    __syncwarp();

    // ---------- backward: y <- J_k^{-1} y with exact state reconstruction ----
    for (int k = NF - 1; k >= 0; k--) {
        bwd_phase2(sm, k * 4 + 2, up, lo, ys0 + 32, ys1 + 32, ys0, ys1, role, jhalf);
        __syncwarp();
        bwd_phase2(sm, k * 4 + 0, lo, up, ys0, ys1, ys0 + 32, ys1 + 32, role, jhalf);
        __syncwarp();
    }

    // ---------- output ----------
#pragma unroll
    for (int si = 0; si < 2; si++) {
        const int samp = si ? samp1 : samp0;
        float* op = gOut + (size_t)samp * 64 + quad * 16;
        const float* yh = (si ? ys1 : ys0) + quad * 16;
#pragma unroll
        for (int i = 0; i < 16; i++) op[i] = yh[i];
    }
}

extern "C" void kernel_launch(void* const* d_in, const int* in_sizes, int n_in,
                              void* d_out, int out_size) {
    const float* x  = (const float*)d_in[0];
    const float* xs = (const float*)d_in[1];
    const float* W0 = (const float*)d_in[2];
    const float* b0 = (const float*)d_in[3];
    const float* W1 = (const float*)d_in[4];
    const float* b1 = (const float*)d_in[5];
    const float* W2 = (const float*)d_in[6];
    const float* b2 = (const float*)d_in[7];
    float* out = (float*)d_out;

    cudaFuncSetAttribute(nf6_kernel, cudaFuncAttributeMaxDynamicSharedMemorySize, SMEM_BYTES);
    nf6_kernel<<<BSZ / SPB, TPB, SMEM_BYTES>>>(x, xs, W0, b0, W1, b1, W2, b2, out);
}

// round 11
// speedup vs baseline: 1.9993x; 1.0003x over previous
#include <cuda_runtime.h>
#include <cuda_bf16.h>

typedef unsigned long long ull;

#define BSZ   16384
#define NF    8
#define TPB   256          // 64 sample-slots/block × 4 lanes; 2 samples/thread
#define SLOTS (TPB / 4)    // 64
#define SPB   (SLOTS * 2)  // 128 samples per block

// skewed smem weight layout (float offsets)
#define W0_RSTR 36
#define W0_STR  296
#define W1_RSTR 12
#define W1_STR  104
#define W2_STR  272
#define B2_STR  36

#define OFF_W0 0
#define OFF_W1 9472
#define OFF_W2 12800
#define OFF_B0 21504
#define OFF_B1 21760
#define OFF_B2 22016
#define OFF_Y  23168
#define Y_STRIDE 68        // 272B: 16B-aligned, 17-bank rotation per slot
#define SMEM_FLOATS (OFF_Y + SPB * Y_STRIDE)
#define SMEM_BYTES  (SMEM_FLOATS * 4)

// ---------------- packed f32x2 helpers ----------------
__device__ __forceinline__ ull ffma2u(ull a, ull b, ull c) {
    asm("fma.rn.f32x2 %0, %1, %2, %0;" : "+l"(c) : "l"(a), "l"(b));
    return c;
}
__device__ __forceinline__ ull f2u(float x, float y) {
    ull u; asm("mov.b64 %0, {%1, %2};" : "=l"(u) : "f"(x), "f"(y)); return u;
}
__device__ __forceinline__ void u2ff(ull u, float& x, float& y) {
    asm("mov.b64 {%0, %1}, %2;" : "=f"(x), "=f"(y) : "l"(u));
}
__device__ __forceinline__ ull ld2u(const float2* p) {
    float2 v = *p; return f2u(v.x, v.y);
}
__device__ __forceinline__ void ld4u(const float4* p, ull& u0, ull& u1) {
    float4 v = *p; u0 = f2u(v.x, v.y); u1 = f2u(v.z, v.w);
}
__device__ __forceinline__ float redu(ull u) {
    float x, y; u2ff(u, x, y); return x + y;
}
// single-MUFU tanh (sm_75+); bwd recomputes identical values so the
// flow inversion stays exact; only Jacobian entries carry ~5e-4 approx error
__device__ __forceinline__ float tanhfast(float x) {
    float r; asm("tanh.approx.f32 %0, %1;" : "=f"(r) : "f"(x));
    return r;
}
__device__ __forceinline__ float shflx(float v, int m) {
    return __shfl_xor_sync(0xFFFFFFFFu, v, m);
}
__device__ __forceinline__ ull shflxu(ull v, int m) {
    return __shfl_xor_sync(0xFFFFFFFFu, v, m);
}
// exchange own 4 values with jhalf partner -> full packed [4]
__device__ __forceinline__ void xch4(float v0, float v1, float v2, float v3,
                                     int jhalf, ull (&out)[4]) {
    ull o0 = f2u(v0, v1), o1 = f2u(v2, v3);
    ull p0 = shflxu(o0, 1), p1 = shflxu(o1, 1);
    out[0] = jhalf ? p0 : o0;
    out[1] = jhalf ? p1 : o1;
    out[2] = jhalf ? o0 : p0;
    out[3] = jhalf ? o1 : p1;
}

// ---------------- forward phase, 2 samples per thread ---------------------
// v[i] = t(a)[i] + v[i]*exp(s(a)[i]); role 0 = t-net, 1 = s-net;
// jhalf owns hidden units [4h,4h+4) and output rows i === jhalf (mod 2)
__device__ __forceinline__ void fwd_phase2(const float* __restrict__ sm, int ibT,
                                           const ull (&a)[2][16], ull (&v)[2][16],
                                           int role, int jhalf) {
    const int ib = ibT + role;
    const float* w0 = sm + OFF_W0 + ib * W0_STR + jhalf * 4 * W0_RSTR;
    const float* w1 = sm + OFF_W1 + ib * W1_STR + jhalf * 4 * W1_RSTR;
    const float* w2 = sm + OFF_W2 + ib * W2_STR;
    const float* b0 = sm + OFF_B0 + ib * 8 + jhalf * 4;
    const float* b1 = sm + OFF_B1 + ib * 8 + jhalf * 4;
    const float* b2 = sm + OFF_B2 + ib * B2_STR;

    // layer 0: own 4 rows over all 32 inputs, weights shared across samples
    ull acc[2][4];
#pragma unroll
    for (int r = 0; r < 4; r++) { acc[0][r] = 0ull; acc[1][r] = 0ull; }
#pragma unroll
    for (int r = 0; r < 4; r++) {
        const float4* rp = (const float4*)(w0 + r * W0_RSTR);
#pragma unroll
        for (int q = 0; q < 8; q++) {
            ull wA, wB; ld4u(rp + q, wA, wB);
            acc[0][r] = ffma2u(wA, a[0][2 * q],     acc[0][r]);
            acc[0][r] = ffma2u(wB, a[0][2 * q + 1], acc[0][r]);
            acc[1][r] = ffma2u(wA, a[1][2 * q],     acc[1][r]);
            acc[1][r] = ffma2u(wB, a[1][2 * q + 1], acc[1][r]);
        }
    }
    ull h1p[2][4];
#pragma unroll
    for (int si = 0; si < 2; si++) {
        float h0 = tanhfast(b0[0] + redu(acc[si][0]));
        float h1 = tanhfast(b0[1] + redu(acc[si][1]));
        float h2 = tanhfast(b0[2] + redu(acc[si][2]));
        float h3 = tanhfast(b0[3] + redu(acc[si][3]));
        xch4(h0, h1, h2, h3, jhalf, h1p[si]);
    }

    // layer 1: own 4 rows, row loaded once for both samples
    float g[2][4];
#pragma unroll
    for (int r = 0; r < 4; r++) {
        const float4* rp = (const float4*)(w1 + r * W1_RSTR);
        ull c0, c1, c2, c3;
        ld4u(rp,     c0, c1);
        ld4u(rp + 1, c2, c3);
#pragma unroll
        for (int si = 0; si < 2; si++) {
            ull m = 0ull;
            m = ffma2u(c0, h1p[si][0], m);
            m = ffma2u(c1, h1p[si][1], m);
            m = ffma2u(c2, h1p[si][2], m);
            m = ffma2u(c3, h1p[si][3], m);
            g[si][r] = tanhfast(b1[r] + redu(m));
        }
    }
    ull h2p[2][4];
    xch4(g[0][0], g[0][1], g[0][2], g[0][3], jhalf, h2p[0]);
    xch4(g[1][0], g[1][1], g[1][2], g[1][3], jhalf, h2p[1]);

    // layer 2: own 16 rows (i = 2r + jhalf), exchange t<->e^s, update v
#pragma unroll
    for (int r = 0; r < 16; r++) {
        const int i = 2 * r + jhalf;
        const float4* rp = (const float4*)(w2 + i * 8);
        ull c0, c1, c2, c3;
        ld4u(rp,     c0, c1);
        ld4u(rp + 1, c2, c3);
#pragma unroll
        for (int si = 0; si < 2; si++) {
            ull m = 0ull;
            m = ffma2u(c0, h2p[si][0], m);
            m = ffma2u(c1, h2p[si][1], m);
            m = ffma2u(c2, h2p[si][2], m);
            m = ffma2u(c3, h2p[si][3], m);
            float val = b2[i] + redu(m);
            if (role) val = __expf(val);
            float other = shflx(val, 2);
            float t = role ? other : val;
            float e = role ? val : other;
            float vx, vy; u2ff(v[si][r], vx, vy);
            float vown = jhalf ? vy : vx;
            float vn = fmaf(vown, e, t);
            float vo = shflx(vn, 1);
            v[si][r] = jhalf ? f2u(vo, vn) : f2u(vn, vo);
        }
    }
}

// ---------------- backward phase, 2 samples per thread --------------------
//   u_new = (u - t(a)) * exp(-s(a))
//   yu    = (yu - (J_t + diag(u - t) J_s) yd) * exp(-s(a))
__device__ __forceinline__ void bwd_phase2(const float* __restrict__ sm, int ibT,
                                           const ull (&a)[2][16], ull (&u)[2][16],
                                           const float* __restrict__ yd0,
                                           const float* __restrict__ yd1,
                                           float* yu0, float* yu1,
                                           int role, int jhalf) {
    const int ib = ibT + role;
    const float* w0 = sm + OFF_W0 + ib * W0_STR + jhalf * 4 * W0_RSTR;
    const float* w1 = sm + OFF_W1 + ib * W1_STR + jhalf * 4 * W1_RSTR;
    const float* w2 = sm + OFF_W2 + ib * W2_STR;
    const float* b0 = sm + OFF_B0 + ib * 8 + jhalf * 4;
    const float* b1 = sm + OFF_B1 + ib * 8 + jhalf * 4;
    const float* b2 = sm + OFF_B2 + ib * B2_STR;

    // fused layer 0: hidden pre-acts (a) + JVP pre-acts (d); q-outer so the
    // direction streams from smem via LDS.128 with no register cache
    ull aH[2][4], aD[2][4];
#pragma unroll
    for (int r = 0; r < 4; r++) {
        aH[0][r] = 0ull; aD[0][r] = 0ull;
        aH[1][r] = 0ull; aD[1][r] = 0ull;
    }
    const float4* yd0v = (const float4*)yd0;
    const float4* yd1v = (const float4*)yd1;
#pragma unroll
    for (int q = 0; q < 8; q++) {
        ull d00, d01, d10, d11;
        ld4u(yd0v + q, d00, d01);
        ld4u(yd1v + q, d10, d11);
        ull a00 = a[0][2 * q], a01 = a[0][2 * q + 1];
        ull a10 = a[1][2 * q], a11 = a[1][2 * q + 1];
#pragma unroll
        for (int r = 0; r < 4; r++) {
            ull wA, wB;
            ld4u((const float4*)(w0 + r * W0_RSTR) + q, wA, wB);
            aH[0][r] = ffma2u(wA, a00, aH[0][r]);
            aD[0][r] = ffma2u(wA, d00, aD[0][r]);
            aH[0][r] = ffma2u(wB, a01, aH[0][r]);
            aD[0][r] = ffma2u(wB, d01, aD[0][r]);
            aH[1][r] = ffma2u(wA, a10, aH[1][r]);
            aD[1][r] = ffma2u(wA, d10, aD[1][r]);
            aH[1][r] = ffma2u(wB, a11, aH[1][r]);
            aD[1][r] = ffma2u(wB, d11, aD[1][r]);
        }
    }
    ull h1p[2][4], pp[2][4];
#pragma unroll
    for (int si = 0; si < 2; si++) {
        float hv[4], pv[4];
#pragma unroll
        for (int r = 0; r < 4; r++) {
            float t = tanhfast(b0[r] + redu(aH[si][r]));
            hv[r] = t;
            pv[r] = (1.f - t * t) * redu(aD[si][r]);
        }
        xch4(hv[0], hv[1], hv[2], hv[3], jhalf, h1p[si]);
        xch4(pv[0], pv[1], pv[2], pv[3], jhalf, pp[si]);
    }

    // fused layer 1: row loaded once, 4 accumulators (H,Q × 2 samples)
    float gv[2][4], qv[2][4];
#pragma unroll
    for (int r = 0; r < 4; r++) {
        const float4* rp = (const float4*)(w1 + r * W1_RSTR);
        ull c0, c1, c2, c3;
        ld4u(rp,     c0, c1);
        ld4u(rp + 1, c2, c3);
#pragma unroll
        for (int si = 0; si < 2; si++) {
            ull mH = 0ull, mQ = 0ull;
            mH = ffma2u(c0, h1p[si][0], mH); mQ = ffma2u(c0, pp[si][0], mQ);
            mH = ffma2u(c1, h1p[si][1], mH); mQ = ffma2u(c1, pp[si][1], mQ);
            mH = ffma2u(c2, h1p[si][2], mH); mQ = ffma2u(c2, pp[si][2], mQ);
            mH = ffma2u(c3, h1p[si][3], mH); mQ = ffma2u(c3, pp[si][3], mQ);
            float t = tanhfast(b1[r] + redu(mH));
            gv[si][r] = t;
            qv[si][r] = (1.f - t * t) * redu(mQ);
        }
    }
    ull h2p[2][4], qp[2][4];
#pragma unroll
    for (int si = 0; si < 2; si++) {
        xch4(gv[si][0], gv[si][1], gv[si][2], gv[si][3], jhalf, h2p[si]);
        xch4(qv[si][0], qv[si][1], qv[si][2], qv[si][3], jhalf, qp[si]);
    }

    // layer 2: own 16 rows, exchange (t,cT)<->(e^-s,dS), inverse update
#pragma unroll
    for (int r = 0; r < 16; r++) {
        const int i = 2 * r + jhalf;
        const float4* rp = (const float4*)(w2 + i * 8);
        ull c0, c1, c2, c3;
        ld4u(rp,     c0, c1);
        ld4u(rp + 1, c2, c3);
#pragma unroll
        for (int si = 0; si < 2; si++) {
            ull mM = 0ull, mX = 0ull;
            mM = ffma2u(c0, h2p[si][0], mM); mX = ffma2u(c0, qp[si][0], mX);
            mM = ffma2u(c1, h2p[si][1], mM); mX = ffma2u(c1, qp[si][1], mX);
            mM = ffma2u(c2, h2p[si][2], mM); mX = ffma2u(c2, qp[si][2], mX);
            mM = ffma2u(c3, h2p[si][3], mM); mX = ffma2u(c3, qp[si][3], mX);
            float rv = b2[i] + redu(mM);   // T: t_i   S: s_i
            float xv = redu(mX);           // T: cT_i  S: dS_i
            if (role) rv = __expf(-rv);    // S sends e^{-s}
            float oA = shflx(rv, 2);
            float oB = shflx(xv, 2);
            float tt = role ? oA : rv;
            float ee = role ? rv : oA;
            float cT = role ? oB : xv;
            float dS = role ? xv : oB;
            float ux, uy; u2ff(u[si][r], ux, uy);
            float uown = jhalf ? uy : ux;
            float dd = uown - tt;          // = u_prev * e^{s}
            float un = dd * ee;
            float cv = cT + dd * dS;       // (C * yd)_i
            if (!role) {
                float* yu = si ? yu1 : yu0;
                yu[i] = (yu[i] - cv) * ee;
            }
            float uo = shflx(un, 1);
            u[si][r] = jhalf ? f2u(uo, un) : f2u(un, uo);
        }
    }
}

__global__ __launch_bounds__(TPB, 1)
void nf6_kernel(const float* __restrict__ gX, const float* __restrict__ gXs,
                const float* __restrict__ gW0, const float* __restrict__ gB0,
                const float* __restrict__ gW1, const float* __restrict__ gB1,
                const float* __restrict__ gW2, const float* __restrict__ gB2,
                float* __restrict__ gOut) {
    extern __shared__ float sm[];
    const int tid = threadIdx.x;

    // cooperative weight load with skewed layout
    for (int i = tid; i < 8192; i += TPB)
        sm[OFF_W0 + (i >> 8) * W0_STR + ((i >> 5) & 7) * W0_RSTR + (i & 31)] = gW0[i];
    for (int i = tid; i < 2048; i += TPB)
        sm[OFF_W1 + (i >> 6) * W1_STR + ((i >> 3) & 7) * W1_RSTR + (i & 7)] = gW1[i];
    for (int i = tid; i < 8192; i += TPB)
        sm[OFF_W2 + (i >> 8) * W2_STR + (i & 255)] = gW2[i];
    for (int i = tid; i < 256;  i += TPB) sm[OFF_B0 + i] = gB0[i];
    for (int i = tid; i < 256;  i += TPB) sm[OFF_B1 + i] = gB1[i];
    for (int i = tid; i < 1024; i += TPB) sm[OFF_B2 + (i >> 5) * B2_STR + (i & 31)] = gB2[i];
    __syncthreads();

    const int quad   = tid & 3;
    const int jhalf  = quad & 1;
    const int role   = (quad >> 1) & 1;
    const int slot   = tid >> 2;                 // 0..63
    const int samp0  = blockIdx.x * SPB + slot;  // this thread's two samples
    const int samp1  = samp0 + SLOTS;

    ull lo[2][16], up[2][16];
    {
        const float2* x0 = (const float2*)(gX + (size_t)samp0 * 64);
        const float2* x1 = (const float2*)(gX + (size_t)samp1 * 64);
#pragma unroll
        for (int m = 0; m < 16; m++) {
            lo[0][m] = ld2u(x0 + m); up[0][m] = ld2u(x0 + 16 + m);
            lo[1][m] = ld2u(x1 + m); up[1][m] = ld2u(x1 + 16 + m);
        }
    }

    // ---------- forward: z = phi(x) ----------
    for (int k = 0; k < NF; k++) {
        fwd_phase2(sm, k * 4 + 0, lo, up, role, jhalf);
        fwd_phase2(sm, k * 4 + 2, up, lo, role, jhalf);
    }

    // ---------- rhs: g = -2 (x - x_star); each lane writes its 16 per sample ----
    float* ys0 = sm + OFF_Y + slot * Y_STRIDE;
    float* ys1 = sm + OFF_Y + (slot + SLOTS) * Y_STRIDE;
#pragma unroll
    for (int si = 0; si < 2; si++) {
        const int samp = si ? samp1 : samp0;
        const float* xp  = gX  + (size_t)samp * 64 + quad * 16;
        const float* xsp = gXs + (size_t)samp * 64 + quad * 16;
        float* yh = (si ? ys1 : ys0) + quad * 16;
#pragma unroll
        for (int i = 0; i < 16; i++) yh[i] = -2.f * (xp[i] - xsp[i]);
    }
    __syncwarp();

    // ---------- backward: y <- J_k^{-1} y with exact state reconstruction ----
    for (int k = NF - 1; k >= 0; k--) {
        bwd_phase2(sm, k * 4 + 2, up, lo, ys0 + 32, ys1 + 32, ys0, ys1, role, jhalf);
        __syncwarp();
        bwd_phase2(sm, k * 4 + 0, lo, up, ys0, ys1, ys0 + 32, ys1 + 32, role, jhalf);
        __syncwarp();
    }

    // ---------- output ----------
#pragma unroll
    for (int si = 0; si < 2; si++) {
        const int samp = si ? samp1 : samp0;
        float* op = gOut + (size_t)samp * 64 + quad * 16;
        const float* yh = (si ? ys1 : ys0) + quad * 16;
#pragma unroll
        for (int i = 0; i < 16; i++) op[i] = yh[i];
    }
}

extern "C" void kernel_launch(void* const* d_in, const int* in_sizes, int n_in,
                              void* d_out, int out_size) {
    const float* x  = (const float*)d_in[0];
    const float* xs = (const float*)d_in[1];
    const float* W0 = (const float*)d_in[2];
    const float* b0 = (const float*)d_in[3];
    const float* W1 = (const float*)d_in[4];
    const float* b1 = (const float*)d_in[5];
    const float* W2 = (const float*)d_in[6];
    const float* b2 = (const float*)d_in[7];
    float* out = (float*)d_out;

    cudaFuncSetAttribute(nf6_kernel, cudaFuncAttributeMaxDynamicSharedMemorySize, SMEM_BYTES);
    nf6_kernel<<<BSZ / SPB, TPB, SMEM_BYTES>>>(x, xs, W0, b0, W1, b1, W2, b2, out);
}